// round 7
// baseline (speedup 1.0000x reference)
#include <cuda_runtime.h>
#include <cuda_bf16.h>
#include <cstdint>

typedef unsigned long long ull;
typedef unsigned int u32;

#define HB (1024*512)

// ---------------- scratch (static __device__, no allocations) ----------------
static __device__ float g_b0[4096];               // b_ih+b_hh
static __device__ float g_bf[4096];               // + W_ih@b_out
static __device__ u32   g_flag[129][4][16];       // per-(t,mT,chunk) producer counters
// weight tiles, gate-paired rows, SW128 pre-swizzled: [src][nT 32][chunk 16][part 2][128x64]
static __device__ __align__(256) __nv_bfloat16 g_wbf[2][32][16][2][8192];
// hidden tiles: [t 0..128][mT 4][chunk 16][part 2][128x64]
static __device__ __align__(256) __nv_bfloat16 g_hbf[129][4][16][2][8192];
// output-weight tiles: [nOT 2][chunk 16][part 2][128x64]
static __device__ __align__(256) __nv_bfloat16 g_obf[2][16][2][8192];
// prep-GEMM operands
static __device__ __align__(256) __nv_bfloat16 g_pA[32][4][2][8192];
static __device__ __align__(256) __nv_bfloat16 g_pB[16][4][2][4096];

// ---------------- helpers ----------------
__device__ __forceinline__ float sigm(float x) { return 1.0f / (1.0f + __expf(-x)); }
__device__ __forceinline__ u32 swz(u32 x) { return x ^ ((x >> 3) & 0x70); }
__device__ __forceinline__ u32 smem_u32(const void* p) {
    u32 a; asm("{ .reg .u64 t; cvta.to.shared.u64 t, %1; cvt.u32.u64 %0, t; }" : "=r"(a) : "l"(p));
    return a;
}
__device__ __forceinline__ void cpa16(u32 dst, const void* src) {
    asm volatile("cp.async.cg.shared.global [%0], [%1], 16;" :: "r"(dst), "l"(src));
}
#define CP_COMMIT() asm volatile("cp.async.commit_group;" ::: "memory")
#define CP_WAIT1()  asm volatile("cp.async.wait_group 1;" ::: "memory")
#define CP_WAIT0()  asm volatile("cp.async.wait_group 0;" ::: "memory")

__device__ __forceinline__ void ldsm4(u32* r, u32 addr) {
    asm volatile("ldmatrix.sync.aligned.m8n8.x4.shared.b16 {%0,%1,%2,%3}, [%4];"
                 : "=r"(r[0]), "=r"(r[1]), "=r"(r[2]), "=r"(r[3]) : "r"(addr));
}
__device__ __forceinline__ void mma_bf16(float* d, const u32* a, const u32* b) {
    asm volatile("mma.sync.aligned.m16n8k16.row.col.f32.bf16.bf16.f32 "
                 "{%0,%1,%2,%3}, {%4,%5,%6,%7}, {%8,%9}, {%0,%1,%2,%3};"
                 : "+f"(d[0]), "+f"(d[1]), "+f"(d[2]), "+f"(d[3])
                 : "r"(a[0]), "r"(a[1]), "r"(a[2]), "r"(a[3]), "r"(b[0]), "r"(b[1]));
}
__device__ __forceinline__ void split_w(float v, __nv_bfloat16& h, __nv_bfloat16& l) {
    h = __float2bfloat16(v);
    l = __float2bfloat16(v - __bfloat162float(h));
}
__device__ __forceinline__ u32 pack_split2(float v0, float v1, u32& lo_out) {
    __nv_bfloat16 h0, l0, h1, l1;
    split_w(v0, h0, l0); split_w(v1, h1, l1);
    lo_out = (u32)__bfloat16_as_ushort(l0) | ((u32)__bfloat16_as_ushort(l1) << 16);
    return (u32)__bfloat16_as_ushort(h0) | ((u32)__bfloat16_as_ushort(h1) << 16);
}
// gate-paired row -> j (j = gate*1024 + cell)
__device__ __forceinline__ int rowj(int nT, int n) {
    int half = n >> 6, m = n & 63;
    return (half * 2 + (m & 1)) * 1024 + nT * 32 + (m >> 1);
}
__device__ __forceinline__ void wait_flag(const u32* p, u32 tgt) {
    u32 v;
    asm volatile("ld.acquire.gpu.global.u32 %0, [%1];" : "=r"(v) : "l"(p) : "memory");
    while (v < tgt) {
        asm volatile("nanosleep.u32 64;");
        asm volatile("ld.acquire.gpu.global.u32 %0, [%1];" : "=r"(v) : "l"(p) : "memory");
    }
}

// ---------------- init flags ----------------
__global__ void init_flags() {
    int i = blockIdx.x * 256 + threadIdx.x;
    if (i < 129 * 4 * 16) ((u32*)g_flag)[i] = 0;
}

// ---------------- prep: biases (warp per j) ----------------
__global__ void prep_bias(const float* __restrict__ Wih, const float* __restrict__ bih,
                          const float* __restrict__ bhh, const float* __restrict__ bout)
{
    int w = threadIdx.x >> 5, lane = threadIdx.x & 31;
    int j = blockIdx.x * 8 + w;
    float acc = 0.f;
#pragma unroll
    for (int i = 0; i < 8; i++) acc += Wih[(size_t)j * 256 + i * 32 + lane] * bout[i * 32 + lane];
#pragma unroll
    for (int o = 16; o; o >>= 1) acc += __shfl_xor_sync(0xFFFFFFFFu, acc, o);
    if (lane == 0) {
        float s = bih[j] + bhh[j];
        g_b0[j] = s;
        g_bf[j] = s + acc;
    }
}

// ---------------- conv: Whh -> g_wbf[0] (warp-per-row, coalesced) ----------------
__global__ void conv_w0(const float* __restrict__ Whh)
{
    int chunk = blockIdx.x, nT = blockIdx.y;
    int w = threadIdx.x >> 5, lane = threadIdx.x & 31;
    char* th = (char*)&g_wbf[0][nT][chunk][0][0];
    char* tl = th + 16384;
#pragma unroll
    for (int r = 0; r < 16; r++) {
        int n = r * 8 + w;
        const float2 v2 = *(const float2*)&Whh[(size_t)rowj(nT, n) * 1024 + chunk * 64 + lane * 2];
        u32 lo, hi = pack_split2(v2.x, v2.y, lo);
        u32 off = swz((u32)(n * 128 + lane * 4));
        *(u32*)(th + off) = hi;
        *(u32*)(tl + off) = lo;
    }
}

// ---------------- conv: Wih -> g_pA ----------------
__global__ void conv_wih(const float* __restrict__ Wih)
{
    int oc = blockIdx.x, nT = blockIdx.y;
    int w = threadIdx.x >> 5, lane = threadIdx.x & 31;
    char* th = (char*)&g_pA[nT][oc][0][0];
    char* tl = th + 16384;
#pragma unroll
    for (int r = 0; r < 16; r++) {
        int n = r * 8 + w;
        const float2 v2 = *(const float2*)&Wih[(size_t)rowj(nT, n) * 256 + oc * 64 + lane * 2];
        u32 lo, hi = pack_split2(v2.x, v2.y, lo);
        u32 off = swz((u32)(n * 128 + lane * 4));
        *(u32*)(th + off) = hi;
        *(u32*)(tl + off) = lo;
    }
}

// ---------------- conv: Wout^T -> g_pB ----------------
__global__ void conv_woutT(const float* __restrict__ Wout)
{
    int oc = blockIdx.x, kc = blockIdx.y;
    int k = threadIdx.x & 63, og = threadIdx.x >> 6;
    char* th = (char*)&g_pB[kc][oc][0][0];
    char* tl = th + 8192;
#pragma unroll
    for (int i = 0; i < 16; i++) {
        int oo = og * 16 + i;
        float v = Wout[(size_t)(oc * 64 + oo) * 1024 + kc * 64 + k];
        __nv_bfloat16 h, l; split_w(v, h, l);
        u32 off = swz((u32)(k * 128 + oo * 2));
        *(__nv_bfloat16*)(th + off) = h;
        *(__nv_bfloat16*)(tl + off) = l;
    }
}

// ---------------- conv: Wout -> g_obf ----------------
__global__ void conv_obf(const float* __restrict__ Wout)
{
    int chunk = blockIdx.x, nOT = blockIdx.y;
    int w = threadIdx.x >> 5, lane = threadIdx.x & 31;
    char* th = (char*)&g_obf[nOT][chunk][0][0];
    char* tl = th + 16384;
#pragma unroll
    for (int r = 0; r < 16; r++) {
        int n = r * 8 + w;
        const float2 v2 = *(const float2*)&Wout[(size_t)(nOT * 128 + n) * 1024 + chunk * 64 + lane * 2];
        u32 lo, hi = pack_split2(v2.x, v2.y, lo);
        u32 off = swz((u32)(n * 128 + lane * 4));
        *(u32*)(th + off) = hi;
        *(u32*)(tl + off) = lo;
    }
}

// ---------------- conv: encoder h0 -> g_hbf[0] ----------------
__global__ void conv_h0(const float* __restrict__ enc)
{
    int chunk = blockIdx.x, mT = blockIdx.y;
    int w = threadIdx.x >> 5, lane = threadIdx.x & 31;
    char* th = (char*)&g_hbf[0][mT][chunk][0][0];
    char* tl = th + 16384;
#pragma unroll
    for (int r = 0; r < 16; r++) {
        int m = r * 8 + w;
        const float2 v2 = *(const float2*)&enc[(size_t)(mT * 128 + m) * 1024 + chunk * 64 + lane * 2];
        u32 lo, hi = pack_split2(v2.x, v2.y, lo);
        u32 off = swz((u32)(m * 128 + lane * 4));
        *(u32*)(th + off) = hi;
        *(u32*)(tl + off) = lo;
    }
}

// ---------------- prep GEMM: g_wbf[1] = split(Whh + Wih @ Wout^T) ----------
#define PREP_SMEM (128*1024 + 64*1024 + 1024)
__global__ __launch_bounds__(256, 1) void prep_mma(const float* __restrict__ Whh)
{
    extern __shared__ char smem[];
    u32 sb = (smem_u32(smem) + 1023) & ~1023u;
    int tid = threadIdx.x, lane = tid & 31, w = tid >> 5;
    int nT = blockIdx.x, kc = blockIdx.y;

    const char* srcA = (const char*)&g_pA[nT][0][0][0];
    const char* srcB = (const char*)&g_pB[kc][0][0][0];
#pragma unroll
    for (int r = 0; r < 32; r++) { int idx = r * 256 + tid; cpa16(sb + idx * 16, srcA + (size_t)idx * 16); }
#pragma unroll
    for (int r = 0; r < 16; r++) { int idx = r * 256 + tid; cpa16(sb + 131072 + idx * 16, srcB + (size_t)idx * 16); }
    CP_COMMIT(); CP_WAIT0();
    __syncthreads();

    int wm = w >> 1, wn = w & 1;
    const int aRow = ((lane >> 3) & 1) * 8 + (lane & 7);
    const int aKh  = lane >> 4;
    const int bRow = (lane >> 4) * 8 + (lane & 7);
    const int bKh  = (lane >> 3) & 1;

    float d[2][4][4] = {};
#pragma unroll
    for (int oc = 0; oc < 4; oc++) {
        u32 stA = sb + oc * 32768;
        u32 stB = sb + 131072 + oc * 16384;
#pragma unroll
        for (int k16 = 0; k16 < 4; k16++) {
            u32 aH[2][4], aL[2][4];
#pragma unroll
            for (int mi = 0; mi < 2; mi++) {
                u32 off = swz((u32)((wm * 32 + mi * 16 + aRow) * 128 + (k16 * 2 + aKh) * 16));
                ldsm4(aH[mi], stA + off);
                ldsm4(aL[mi], stA + 16384 + off);
            }
            u32 bH[2][4], bL[2][4];
#pragma unroll
            for (int bi = 0; bi < 2; bi++) {
                u32 off = swz((u32)((wn * 32 + bi * 16 + bRow) * 128 + (k16 * 2 + bKh) * 16));
                ldsm4(bH[bi], stB + off);
                ldsm4(bL[bi], stB + 8192 + off);
            }
#pragma unroll
            for (int mi = 0; mi < 2; mi++)
#pragma unroll
                for (int nj = 0; nj < 4; nj++) {
                    mma_bf16(d[mi][nj], aH[mi], &bH[nj >> 1][(nj & 1) * 2]);
                    mma_bf16(d[mi][nj], aH[mi], &bL[nj >> 1][(nj & 1) * 2]);
                    mma_bf16(d[mi][nj], aL[mi], &bH[nj >> 1][(nj & 1) * 2]);
                }
        }
    }

    char* th = (char*)&g_wbf[1][nT][kc][0][0];
    char* tl = th + 16384;
#pragma unroll
    for (int mi = 0; mi < 2; mi++)
#pragma unroll
        for (int nj = 0; nj < 4; nj++)
#pragma unroll
            for (int rh = 0; rh < 2; rh++) {
                int n = wm * 32 + mi * 16 + (lane >> 2) + rh * 8;
                int j = rowj(nT, n);
                int k0l = wn * 32 + nj * 8 + 2 * (lane & 3);
                const float* wr = Whh + (size_t)j * 1024 + kc * 64 + k0l;
                u32 lo, hi = pack_split2(d[mi][nj][rh * 2 + 0] + wr[0],
                                         d[mi][nj][rh * 2 + 1] + wr[1], lo);
                u32 off = swz((u32)(n * 128 + k0l * 2));
                *(u32*)(th + off) = hi;
                *(u32*)(tl + off) = lo;
            }
}

// ---------------- persistent LSTM with per-chunk dataflow flags ----------------
#define LSTAGE 65536
#define LSTM_SMEM (2*LSTAGE + 1024)
__global__ __launch_bounds__(256, 1) void lstm_persist()
{
    extern __shared__ char smem[];
    u32 sb = (smem_u32(smem) + 1023) & ~1023u;
    const int tid = threadIdx.x, lane = tid & 31, w = tid >> 5;
    const int mT = blockIdx.x, nT = blockIdx.y;
    const int wm = w >> 2, wn = w & 3;
    const int aRow = ((lane >> 3) & 1) * 8 + (lane & 7);
    const int aKh  = lane >> 4;
    const int bRow = (lane >> 4) * 8 + (lane & 7);
    const int bKh  = (lane >> 3) & 1;

    auto fillA = [&](int c, int s, const char* src) {
#pragma unroll
        for (int r = 0; r < 8; r++) {
            int idx = r * 256 + tid;
            cpa16(sb + s * LSTAGE + idx * 16, src + (size_t)c * 32768 + idx * 16);
        }
    };
    auto fillB = [&](int c, int s, const char* src) {
#pragma unroll
        for (int r = 0; r < 8; r++) {
            int idx = r * 256 + tid;
            cpa16(sb + s * LSTAGE + 32768 + idx * 16, src + (size_t)c * 32768 + idx * 16);
        }
    };

    float bZ[2][4], bF[2][4];
#pragma unroll
    for (int cp = 0; cp < 2; cp++) {
        int cell = nT * 32 + wn * 8 + cp * 4 + (lane & 3);
#pragma unroll
        for (int g = 0; g < 4; g++) {
            bZ[cp][g] = g_b0[g * 1024 + cell];
            bF[cp][g] = g_bf[g * 1024 + cell];
        }
    }

    float creg[4][2][2];
#pragma unroll
    for (int mi = 0; mi < 4; mi++)
#pragma unroll
        for (int rh = 0; rh < 2; rh++)
#pragma unroll
            for (int cp = 0; cp < 2; cp++) creg[mi][rh][cp] = 0.f;

    const char* srcBn = (const char*)&g_wbf[1][nT][0][0][0];

    // prologue: B0,B1,A0,A1 (group order matters for wait_group 1)
    {
        const char* B1 = (const char*)&g_wbf[0][nT][0][0][0];
        const char* A1 = (const char*)&g_hbf[0][mT][0][0][0];
        fillB(0, 0, B1); CP_COMMIT();
        fillB(1, 1, B1); CP_COMMIT();
        fillA(0, 0, A1); CP_COMMIT();
        fillA(1, 1, A1); CP_COMMIT();
    }

    for (int t = 1; t <= 128; t++) {
        const int first = (t == 1);
        const char* srcA = (const char*)&g_hbf[t - 1][mT][0][0][0];
        const char* srcB = first ? (const char*)&g_wbf[0][nT][0][0][0] : srcBn;

        float d[4][4][4];
#pragma unroll
        for (int mi = 0; mi < 4; mi++)
#pragma unroll
            for (int nj = 0; nj < 4; nj++)
#pragma unroll
                for (int q = 0; q < 4; q++) d[mi][nj][q] = 0.f;

        for (int c = 0; c < 16; c++) {
            int s = c & 1;
            CP_WAIT1();
            __syncthreads();
            u32 stA = sb + s * LSTAGE;
            u32 stB = stA + 32768;
#pragma unroll
            for (int k16 = 0; k16 < 4; k16++) {
                u32 aH[4][4], aL[4][4];
#pragma unroll
                for (int mi = 0; mi < 4; mi++) {
                    u32 off = swz((u32)((wm * 64 + mi * 16 + aRow) * 128 + (k16 * 2 + aKh) * 16));
                    ldsm4(aH[mi], stA + off);
                    ldsm4(aL[mi], stA + 16384 + off);
                }
                u32 bIFh[4], bIFl[4], bGOh[4], bGOl[4];
                {
                    u32 offIF = swz((u32)((wn * 16 + bRow) * 128 + (k16 * 2 + bKh) * 16));
                    u32 offGO = swz((u32)((64 + wn * 16 + bRow) * 128 + (k16 * 2 + bKh) * 16));
                    ldsm4(bIFh, stB + offIF); ldsm4(bIFl, stB + 16384 + offIF);
                    ldsm4(bGOh, stB + offGO); ldsm4(bGOl, stB + 16384 + offGO);
                }
#pragma unroll
                for (int mi = 0; mi < 4; mi++)
#pragma unroll
                    for (int nj = 0; nj < 2; nj++) {
                        mma_bf16(d[mi][nj],     aH[mi], &bIFh[nj * 2]);
                        mma_bf16(d[mi][nj],     aH[mi], &bIFl[nj * 2]);
                        mma_bf16(d[mi][nj],     aL[mi], &bIFh[nj * 2]);
                        mma_bf16(d[mi][nj + 2], aH[mi], &bGOh[nj * 2]);
                        mma_bf16(d[mi][nj + 2], aH[mi], &bGOl[nj * 2]);
                        mma_bf16(d[mi][nj + 2], aL[mi], &bGOh[nj * 2]);
                    }
            }
            __syncthreads();
            if (c + 2 < 16) {
                if (t > 1) wait_flag(&g_flag[t - 1][mT][c + 2], 2);   // usually already set
                fillA(c + 2, s, srcA);
                fillB(c + 2, s, srcB);
            } else if (t < 128) {
                fillB(c - 14, s, srcBn);     // next step's B chunk 0/1 (h-independent)
            }
            CP_COMMIT();
        }

        // ---- epilogue: LSTM cell update (c in regs) + emit next A tile ----
        {
            const int chunk = nT >> 1;
            char* dh = (char*)&g_hbf[t][mT][chunk][0][0];
            char* dl = dh + 16384;
#pragma unroll
            for (int mi = 0; mi < 4; mi++)
#pragma unroll
                for (int rh = 0; rh < 2; rh++) {
                    int bl = wm * 64 + mi * 16 + (lane >> 2) + rh * 8;
#pragma unroll
                    for (int cp = 0; cp < 2; cp++) {
                        int cl = wn * 8 + cp * 4 + (lane & 3);
                        float gi = d[mi][cp][rh * 2 + 0]     + (first ? bZ[cp][0] : bF[cp][0]);
                        float gf = d[mi][cp][rh * 2 + 1]     + (first ? bZ[cp][1] : bF[cp][1]);
                        float gg = d[mi][cp + 2][rh * 2 + 0] + (first ? bZ[cp][2] : bF[cp][2]);
                        float go = d[mi][cp + 2][rh * 2 + 1] + (first ? bZ[cp][3] : bF[cp][3]);
                        float cold = first ? 0.f : creg[mi][rh][cp];
                        float cn = sigm(gf) * cold + sigm(gi) * tanhf(gg);
                        float hn = sigm(go) * tanhf(cn);
                        creg[mi][rh][cp] = cn;
                        __nv_bfloat16 hh, hl; split_w(hn, hh, hl);
                        int kin = (nT & 1) * 32 + cl;
                        u32 off = swz((u32)(bl * 128 + kin * 2));
                        *(__nv_bfloat16*)(dh + off) = hh;
                        *(__nv_bfloat16*)(dl + off) = hl;
                    }
                }
        }

        if (t < 128) {
            __syncthreads();                         // all epilogue STGs issued in CTA
            if (tid == 0) {
                asm volatile("fence.release.gpu;" ::: "memory");
                asm volatile("red.relaxed.gpu.global.add.u32 [%0], %1;"
                             :: "l"(&g_flag[t][mT][nT >> 1]), "r"(1u) : "memory");
            }
            const char* An = (const char*)&g_hbf[t][mT][0][0][0];
            wait_flag(&g_flag[t][mT][0], 2);
            fillA(0, 0, An); CP_COMMIT();
            wait_flag(&g_flag[t][mT][1], 2);
            fillA(1, 1, An); CP_COMMIT();
        }
    }
}

// ---------------- output GEMM: out[b][t][o] = h_{t+1} @ Wout^T + b_out ------
__global__ __launch_bounds__(256, 1) void out_mma(const float* __restrict__ bout,
                                                  float* __restrict__ out)
{
    extern __shared__ char smem[];
    u32 sb = (smem_u32(smem) + 1023) & ~1023u;
    int tid = threadIdx.x, lane = tid & 31, w = tid >> 5;
    int mT = blockIdx.x, nOT = blockIdx.y, t = blockIdx.z;

    const char* srcA = (const char*)&g_hbf[t + 1][mT][0][0][0];
    const char* srcB = (const char*)&g_obf[nOT][0][0][0];

#pragma unroll
    for (int pc = 0; pc < 2; pc++) {
        u32 stg = sb + pc * LSTAGE;
        const char* a = srcA + (size_t)pc * 32768;
        const char* b = srcB + (size_t)pc * 32768;
#pragma unroll
        for (int r = 0; r < 8; r++) { int idx = r * 256 + tid; cpa16(stg + idx * 16, a + (size_t)idx * 16); }
#pragma unroll
        for (int r = 0; r < 8; r++) { int idx = r * 256 + tid; cpa16(stg + 32768 + idx * 16, b + (size_t)idx * 16); }
        CP_COMMIT();
    }

    int wm = w >> 2, wn = w & 3;
    const int aRow = ((lane >> 3) & 1) * 8 + (lane & 7);
    const int aKh  = lane >> 4;
    const int bRow = (lane >> 4) * 8 + (lane & 7);
    const int bKh  = (lane >> 3) & 1;

    float d[4][4][4] = {};

    for (int c = 0; c < 16; c++) {
        int s = c & 1;
        CP_WAIT1();
        __syncthreads();
        u32 stA = sb + s * LSTAGE;
        u32 stB = stA + 32768;
#pragma unroll
        for (int k16 = 0; k16 < 4; k16++) {
            u32 aH[4][4], aL[4][4];
#pragma unroll
            for (int mi = 0; mi < 4; mi++) {
                u32 off = swz((u32)((wm * 64 + mi * 16 + aRow) * 128 + (k16 * 2 + aKh) * 16));
                ldsm4(aH[mi], stA + off);
                ldsm4(aL[mi], stA + 16384 + off);
            }
            u32 bH[2][4], bL[2][4];
#pragma unroll
            for (int bi = 0; bi < 2; bi++) {
                u32 off = swz((u32)((wn * 32 + bi * 16 + bRow) * 128 + (k16 * 2 + bKh) * 16));
                ldsm4(bH[bi], stB + off);
                ldsm4(bL[bi], stB + 16384 + off);
            }
#pragma unroll
            for (int mi = 0; mi < 4; mi++)
#pragma unroll
                for (int nj = 0; nj < 4; nj++) {
                    mma_bf16(d[mi][nj], aH[mi], &bH[nj >> 1][(nj & 1) * 2]);
                    mma_bf16(d[mi][nj], aH[mi], &bL[nj >> 1][(nj & 1) * 2]);
                    mma_bf16(d[mi][nj], aL[mi], &bH[nj >> 1][(nj & 1) * 2]);
                }
        }
        __syncthreads();
        if (c + 2 < 16) {
            u32 stg = sb + s * LSTAGE;
            const char* a = srcA + (size_t)(c + 2) * 32768;
            const char* b = srcB + (size_t)(c + 2) * 32768;
#pragma unroll
            for (int r = 0; r < 8; r++) { int idx = r * 256 + tid; cpa16(stg + idx * 16, a + (size_t)idx * 16); }
#pragma unroll
            for (int r = 0; r < 8; r++) { int idx = r * 256 + tid; cpa16(stg + 32768 + idx * 16, b + (size_t)idx * 16); }
        }
        CP_COMMIT();
    }

#pragma unroll
    for (int mi = 0; mi < 4; mi++)
#pragma unroll
        for (int nj = 0; nj < 4; nj++)
#pragma unroll
            for (int rh = 0; rh < 2; rh++) {
                int bl = wm * 64 + mi * 16 + (lane >> 2) + rh * 8;
                int b = mT * 128 + bl;
                int o = nOT * 128 + wn * 32 + nj * 8 + 2 * (lane & 3);
                float2 v = make_float2(d[mi][nj][rh * 2 + 0] + bout[o],
                                       d[mi][nj][rh * 2 + 1] + bout[o + 1]);
                *(float2*)&out[(size_t)b * 32768 + (size_t)t * 256 + o] = v;
            }
}

// ---------------- launch ----------------
extern "C" void kernel_launch(void* const* d_in, const int* in_sizes, int n_in,
                              void* d_out, int out_size)
{
    const float *enc = nullptr, *Wih = nullptr, *Whh = nullptr;
    const float *bih = nullptr, *bhh = nullptr, *Wout = nullptr, *bout = nullptr;
    for (int i = 0; i < n_in; i++) {
        int s = in_sizes[i];
        if      (s == 512 * 1024)  enc  = (const float*)d_in[i];
        else if (s == 4096 * 256)  Wih  = (const float*)d_in[i];
        else if (s == 4096 * 1024) Whh  = (const float*)d_in[i];
        else if (s == 4096)        { if (!bih) bih = (const float*)d_in[i]; else bhh = (const float*)d_in[i]; }
        else if (s == 256 * 1024)  Wout = (const float*)d_in[i];
        else if (s == 256)         bout = (const float*)d_in[i];
    }
    if (!enc || !Wih || !Whh || !bih || !bhh || !Wout || !bout) return;

    cudaFuncSetAttribute(prep_mma,     cudaFuncAttributeMaxDynamicSharedMemorySize, PREP_SMEM);
    cudaFuncSetAttribute(lstm_persist, cudaFuncAttributeMaxDynamicSharedMemorySize, LSTM_SMEM);
    cudaFuncSetAttribute(out_mma,      cudaFuncAttributeMaxDynamicSharedMemorySize, LSTM_SMEM);

    init_flags<<<33, 256>>>();
    prep_bias<<<512, 256>>>(Wih, bih, bhh, bout);
    conv_w0<<<dim3(16, 32), 256>>>(Whh);
    conv_wih<<<dim3(4, 32), 256>>>(Wih);
    conv_woutT<<<dim3(4, 16), 256>>>(Wout);
    conv_obf<<<dim3(16, 2), 256>>>(Wout);
    conv_h0<<<dim3(16, 4), 256>>>(enc);
    prep_mma<<<dim3(32, 16), 256, PREP_SMEM>>>(Whh);

    lstm_persist<<<dim3(4, 32), 256, LSTM_SMEM>>>();

    out_mma<<<dim3(4, 2, 128), 256, LSTM_SMEM>>>(bout, (float*)d_out);
    (void)out_size;
}

// round 8
// speedup vs baseline: 1.0661x; 1.0661x over previous
#include <cuda_runtime.h>
#include <cuda_bf16.h>
#include <cstdint>

typedef unsigned long long ull;
typedef unsigned int u32;

#define HB (1024*512)

// ---------------- scratch (static __device__, no allocations) ----------------
static __device__ float g_b0[4096];               // b_ih+b_hh
static __device__ float g_bf[4096];               // + W_ih@b_out
static __device__ u32   g_bar[516];               // per-(t,mT) arrival counters
// weight tiles, gate-paired rows, SW128 pre-swizzled: [src][nT 32][chunk 16][part 2][128x64]
static __device__ __align__(256) __nv_bfloat16 g_wbf[2][32][16][2][8192];
// hidden tiles: [t 0..128][mT 4][chunk 16][part 2][128x64]
static __device__ __align__(256) __nv_bfloat16 g_hbf[129][4][16][2][8192];
// output-weight tiles: [nOT 2][chunk 16][part 2][128x64]
static __device__ __align__(256) __nv_bfloat16 g_obf[2][16][2][8192];
// prep-GEMM operands
static __device__ __align__(256) __nv_bfloat16 g_pA[32][4][2][8192];
static __device__ __align__(256) __nv_bfloat16 g_pB[16][4][2][4096];

// ---------------- helpers ----------------
__device__ __forceinline__ float sigm(float x) { return 1.0f / (1.0f + __expf(-x)); }
__device__ __forceinline__ u32 swz(u32 x) { return x ^ ((x >> 3) & 0x70); }
__device__ __forceinline__ u32 smem_u32(const void* p) {
    u32 a; asm("{ .reg .u64 t; cvta.to.shared.u64 t, %1; cvt.u32.u64 %0, t; }" : "=r"(a) : "l"(p));
    return a;
}
__device__ __forceinline__ void cpa16(u32 dst, const void* src) {
    asm volatile("cp.async.cg.shared.global [%0], [%1], 16;" :: "r"(dst), "l"(src));
}
#define CP_COMMIT() asm volatile("cp.async.commit_group;" ::: "memory")
#define CP_WAIT1()  asm volatile("cp.async.wait_group 1;" ::: "memory")
#define CP_WAIT0()  asm volatile("cp.async.wait_group 0;" ::: "memory")

__device__ __forceinline__ void ldsm4(u32* r, u32 addr) {
    asm volatile("ldmatrix.sync.aligned.m8n8.x4.shared.b16 {%0,%1,%2,%3}, [%4];"
                 : "=r"(r[0]), "=r"(r[1]), "=r"(r[2]), "=r"(r[3]) : "r"(addr));
}
__device__ __forceinline__ void mma_bf16(float* d, const u32* a, const u32* b) {
    asm volatile("mma.sync.aligned.m16n8k16.row.col.f32.bf16.bf16.f32 "
                 "{%0,%1,%2,%3}, {%4,%5,%6,%7}, {%8,%9}, {%0,%1,%2,%3};"
                 : "+f"(d[0]), "+f"(d[1]), "+f"(d[2]), "+f"(d[3])
                 : "r"(a[0]), "r"(a[1]), "r"(a[2]), "r"(a[3]), "r"(b[0]), "r"(b[1]));
}
__device__ __forceinline__ void split_w(float v, __nv_bfloat16& h, __nv_bfloat16& l) {
    h = __float2bfloat16(v);
    l = __float2bfloat16(v - __bfloat162float(h));
}
__device__ __forceinline__ u32 pack_split2(float v0, float v1, u32& lo_out) {
    __nv_bfloat16 h0, l0, h1, l1;
    split_w(v0, h0, l0); split_w(v1, h1, l1);
    lo_out = (u32)__bfloat16_as_ushort(l0) | ((u32)__bfloat16_as_ushort(l1) << 16);
    return (u32)__bfloat16_as_ushort(h0) | ((u32)__bfloat16_as_ushort(h1) << 16);
}
// gate-paired row -> j (j = gate*1024 + cell)
__device__ __forceinline__ int rowj(int nT, int n) {
    int half = n >> 6, m = n & 63;
    return (half * 2 + (m & 1)) * 1024 + nT * 32 + (m >> 1);
}

// ---------------- init barrier counters ----------------
__global__ void init_bar() {
    int i = blockIdx.x * 256 + threadIdx.x;
    if (i < 516) g_bar[i] = 0;
}

// ---------------- prep: biases (warp per j) ----------------
__global__ void prep_bias(const float* __restrict__ Wih, const float* __restrict__ bih,
                          const float* __restrict__ bhh, const float* __restrict__ bout)
{
    int w = threadIdx.x >> 5, lane = threadIdx.x & 31;
    int j = blockIdx.x * 8 + w;
    float acc = 0.f;
#pragma unroll
    for (int i = 0; i < 8; i++) acc += Wih[(size_t)j * 256 + i * 32 + lane] * bout[i * 32 + lane];
#pragma unroll
    for (int o = 16; o; o >>= 1) acc += __shfl_xor_sync(0xFFFFFFFFu, acc, o);
    if (lane == 0) {
        float s = bih[j] + bhh[j];
        g_b0[j] = s;
        g_bf[j] = s + acc;
    }
}

// ---------------- conv: Whh -> g_wbf[0] (warp-per-row, coalesced) ----------------
__global__ void conv_w0(const float* __restrict__ Whh)
{
    int chunk = blockIdx.x, nT = blockIdx.y;
    int w = threadIdx.x >> 5, lane = threadIdx.x & 31;
    char* th = (char*)&g_wbf[0][nT][chunk][0][0];
    char* tl = th + 16384;
#pragma unroll
    for (int r = 0; r < 16; r++) {
        int n = r * 8 + w;
        const float2 v2 = *(const float2*)&Whh[(size_t)rowj(nT, n) * 1024 + chunk * 64 + lane * 2];
        u32 lo, hi = pack_split2(v2.x, v2.y, lo);
        u32 off = swz((u32)(n * 128 + lane * 4));
        *(u32*)(th + off) = hi;
        *(u32*)(tl + off) = lo;
    }
}

// ---------------- conv: Wih -> g_pA ----------------
__global__ void conv_wih(const float* __restrict__ Wih)
{
    int oc = blockIdx.x, nT = blockIdx.y;
    int w = threadIdx.x >> 5, lane = threadIdx.x & 31;
    char* th = (char*)&g_pA[nT][oc][0][0];
    char* tl = th + 16384;
#pragma unroll
    for (int r = 0; r < 16; r++) {
        int n = r * 8 + w;
        const float2 v2 = *(const float2*)&Wih[(size_t)rowj(nT, n) * 256 + oc * 64 + lane * 2];
        u32 lo, hi = pack_split2(v2.x, v2.y, lo);
        u32 off = swz((u32)(n * 128 + lane * 4));
        *(u32*)(th + off) = hi;
        *(u32*)(tl + off) = lo;
    }
}

// ---------------- conv: Wout^T -> g_pB ----------------
__global__ void conv_woutT(const float* __restrict__ Wout)
{
    int oc = blockIdx.x, kc = blockIdx.y;
    int k = threadIdx.x & 63, og = threadIdx.x >> 6;
    char* th = (char*)&g_pB[kc][oc][0][0];
    char* tl = th + 8192;
#pragma unroll
    for (int i = 0; i < 16; i++) {
        int oo = og * 16 + i;
        float v = Wout[(size_t)(oc * 64 + oo) * 1024 + kc * 64 + k];
        __nv_bfloat16 h, l; split_w(v, h, l);
        u32 off = swz((u32)(k * 128 + oo * 2));
        *(__nv_bfloat16*)(th + off) = h;
        *(__nv_bfloat16*)(tl + off) = l;
    }
}

// ---------------- conv: Wout -> g_obf ----------------
__global__ void conv_obf(const float* __restrict__ Wout)
{
    int chunk = blockIdx.x, nOT = blockIdx.y;
    int w = threadIdx.x >> 5, lane = threadIdx.x & 31;
    char* th = (char*)&g_obf[nOT][chunk][0][0];
    char* tl = th + 16384;
#pragma unroll
    for (int r = 0; r < 16; r++) {
        int n = r * 8 + w;
        const float2 v2 = *(const float2*)&Wout[(size_t)(nOT * 128 + n) * 1024 + chunk * 64 + lane * 2];
        u32 lo, hi = pack_split2(v2.x, v2.y, lo);
        u32 off = swz((u32)(n * 128 + lane * 4));
        *(u32*)(th + off) = hi;
        *(u32*)(tl + off) = lo;
    }
}

// ---------------- conv: encoder h0 -> g_hbf[0] ----------------
__global__ void conv_h0(const float* __restrict__ enc)
{
    int chunk = blockIdx.x, mT = blockIdx.y;
    int w = threadIdx.x >> 5, lane = threadIdx.x & 31;
    char* th = (char*)&g_hbf[0][mT][chunk][0][0];
    char* tl = th + 16384;
#pragma unroll
    for (int r = 0; r < 16; r++) {
        int m = r * 8 + w;
        const float2 v2 = *(const float2*)&enc[(size_t)(mT * 128 + m) * 1024 + chunk * 64 + lane * 2];
        u32 lo, hi = pack_split2(v2.x, v2.y, lo);
        u32 off = swz((u32)(m * 128 + lane * 4));
        *(u32*)(th + off) = hi;
        *(u32*)(tl + off) = lo;
    }
}

// ---------------- prep GEMM: g_wbf[1] = split(Whh + Wih @ Wout^T) ----------
#define PREP_SMEM (128*1024 + 64*1024 + 1024)
__global__ __launch_bounds__(256, 1) void prep_mma(const float* __restrict__ Whh)
{
    extern __shared__ char smem[];
    u32 sb = (smem_u32(smem) + 1023) & ~1023u;
    int tid = threadIdx.x, lane = tid & 31, w = tid >> 5;
    int nT = blockIdx.x, kc = blockIdx.y;

    const char* srcA = (const char*)&g_pA[nT][0][0][0];
    const char* srcB = (const char*)&g_pB[kc][0][0][0];
#pragma unroll
    for (int r = 0; r < 32; r++) { int idx = r * 256 + tid; cpa16(sb + idx * 16, srcA + (size_t)idx * 16); }
#pragma unroll
    for (int r = 0; r < 16; r++) { int idx = r * 256 + tid; cpa16(sb + 131072 + idx * 16, srcB + (size_t)idx * 16); }
    CP_COMMIT(); CP_WAIT0();
    __syncthreads();

    int wm = w >> 1, wn = w & 1;
    const int aRow = ((lane >> 3) & 1) * 8 + (lane & 7);
    const int aKh  = lane >> 4;
    const int bRow = (lane >> 4) * 8 + (lane & 7);
    const int bKh  = (lane >> 3) & 1;

    float d[2][4][4] = {};
#pragma unroll
    for (int oc = 0; oc < 4; oc++) {
        u32 stA = sb + oc * 32768;
        u32 stB = sb + 131072 + oc * 16384;
#pragma unroll
        for (int k16 = 0; k16 < 4; k16++) {
            u32 aH[2][4], aL[2][4];
#pragma unroll
            for (int mi = 0; mi < 2; mi++) {
                u32 off = swz((u32)((wm * 32 + mi * 16 + aRow) * 128 + (k16 * 2 + aKh) * 16));
                ldsm4(aH[mi], stA + off);
                ldsm4(aL[mi], stA + 16384 + off);
            }
            u32 bH[2][4], bL[2][4];
#pragma unroll
            for (int bi = 0; bi < 2; bi++) {
                u32 off = swz((u32)((wn * 32 + bi * 16 + bRow) * 128 + (k16 * 2 + bKh) * 16));
                ldsm4(bH[bi], stB + off);
                ldsm4(bL[bi], stB + 8192 + off);
            }
#pragma unroll
            for (int mi = 0; mi < 2; mi++)
#pragma unroll
                for (int nj = 0; nj < 4; nj++) {
                    mma_bf16(d[mi][nj], aH[mi], &bH[nj >> 1][(nj & 1) * 2]);
                    mma_bf16(d[mi][nj], aH[mi], &bL[nj >> 1][(nj & 1) * 2]);
                    mma_bf16(d[mi][nj], aL[mi], &bH[nj >> 1][(nj & 1) * 2]);
                }
        }
    }

    char* th = (char*)&g_wbf[1][nT][kc][0][0];
    char* tl = th + 16384;
#pragma unroll
    for (int mi = 0; mi < 2; mi++)
#pragma unroll
        for (int nj = 0; nj < 4; nj++)
#pragma unroll
            for (int rh = 0; rh < 2; rh++) {
                int n = wm * 32 + mi * 16 + (lane >> 2) + rh * 8;
                int j = rowj(nT, n);
                int k0l = wn * 32 + nj * 8 + 2 * (lane & 3);
                const float* wr = Whh + (size_t)j * 1024 + kc * 64 + k0l;
                u32 lo, hi = pack_split2(d[mi][nj][rh * 2 + 0] + wr[0],
                                         d[mi][nj][rh * 2 + 1] + wr[1], lo);
                u32 off = swz((u32)(n * 128 + k0l * 2));
                *(u32*)(th + off) = hi;
                *(u32*)(tl + off) = lo;
            }
}

// ---------------- persistent LSTM: all 128 steps in one kernel ----------------
// grid (4 mT, 32 nT) = 128 CTAs, all resident. Per-group (mT) release/acquire barrier.
// c state in registers. B chunks 0/1 of next step prefetched during drain.
#define LSTAGE 65536
#define LSTM_SMEM (2*LSTAGE + 1024)
__global__ __launch_bounds__(256, 1) void lstm_persist()
{
    extern __shared__ char smem[];
    u32 sb = (smem_u32(smem) + 1023) & ~1023u;
    const int tid = threadIdx.x, lane = tid & 31, w = tid >> 5;
    const int mT = blockIdx.x, nT = blockIdx.y;
    const int wm = w >> 2, wn = w & 3;
    const int aRow = ((lane >> 3) & 1) * 8 + (lane & 7);
    const int aKh  = lane >> 4;
    const int bRow = (lane >> 4) * 8 + (lane & 7);
    const int bKh  = (lane >> 3) & 1;

    auto fillA = [&](int c, int s, const char* src) {
#pragma unroll
        for (int r = 0; r < 8; r++) {
            int idx = r * 256 + tid;
            cpa16(sb + s * LSTAGE + idx * 16, src + (size_t)c * 32768 + idx * 16);
        }
    };
    auto fillB = [&](int c, int s, const char* src) {
#pragma unroll
        for (int r = 0; r < 8; r++) {
            int idx = r * 256 + tid;
            cpa16(sb + s * LSTAGE + 32768 + idx * 16, src + (size_t)c * 32768 + idx * 16);
        }
    };

    float bZ[2][4], bF[2][4];
#pragma unroll
    for (int cp = 0; cp < 2; cp++) {
        int cell = nT * 32 + wn * 8 + cp * 4 + (lane & 3);
#pragma unroll
        for (int g = 0; g < 4; g++) {
            bZ[cp][g] = g_b0[g * 1024 + cell];
            bF[cp][g] = g_bf[g * 1024 + cell];
        }
    }

    float creg[4][2][2];
#pragma unroll
    for (int mi = 0; mi < 4; mi++)
#pragma unroll
        for (int rh = 0; rh < 2; rh++)
#pragma unroll
            for (int cp = 0; cp < 2; cp++) creg[mi][rh][cp] = 0.f;

    const char* srcBn = (const char*)&g_wbf[1][nT][0][0][0];

    // prologue: B0,B1,A0,A1 as 4 groups (order matters for wait_group 1)
    {
        const char* B1 = (const char*)&g_wbf[0][nT][0][0][0];
        const char* A1 = (const char*)&g_hbf[0][mT][0][0][0];
        fillB(0, 0, B1); CP_COMMIT();
        fillB(1, 1, B1); CP_COMMIT();
        fillA(0, 0, A1); CP_COMMIT();
        fillA(1, 1, A1); CP_COMMIT();
    }

    for (int t = 1; t <= 128; t++) {
        const int first = (t == 1);
        const char* srcA = (const char*)&g_hbf[t - 1][mT][0][0][0];
        const char* srcB = first ? (const char*)&g_wbf[0][nT][0][0][0] : srcBn;

        float d[4][4][4];
#pragma unroll
        for (int mi = 0; mi < 4; mi++)
#pragma unroll
            for (int nj = 0; nj < 4; nj++)
#pragma unroll
                for (int q = 0; q < 4; q++) d[mi][nj][q] = 0.f;

        for (int c = 0; c < 16; c++) {
            int s = c & 1;
            CP_WAIT1();
            __syncthreads();
            u32 stA = sb + s * LSTAGE;
            u32 stB = stA + 32768;
#pragma unroll
            for (int k16 = 0; k16 < 4; k16++) {
                u32 aH[4][4], aL[4][4];
#pragma unroll
                for (int mi = 0; mi < 4; mi++) {
                    u32 off = swz((u32)((wm * 64 + mi * 16 + aRow) * 128 + (k16 * 2 + aKh) * 16));
                    ldsm4(aH[mi], stA + off);
                    ldsm4(aL[mi], stA + 16384 + off);
                }
                u32 bIFh[4], bIFl[4], bGOh[4], bGOl[4];
                {
                    u32 offIF = swz((u32)((wn * 16 + bRow) * 128 + (k16 * 2 + bKh) * 16));
                    u32 offGO = swz((u32)((64 + wn * 16 + bRow) * 128 + (k16 * 2 + bKh) * 16));
                    ldsm4(bIFh, stB + offIF); ldsm4(bIFl, stB + 16384 + offIF);
                    ldsm4(bGOh, stB + offGO); ldsm4(bGOl, stB + 16384 + offGO);
                }
#pragma unroll
                for (int mi = 0; mi < 4; mi++)
#pragma unroll
                    for (int nj = 0; nj < 2; nj++) {
                        mma_bf16(d[mi][nj],     aH[mi], &bIFh[nj * 2]);
                        mma_bf16(d[mi][nj],     aH[mi], &bIFl[nj * 2]);
                        mma_bf16(d[mi][nj],     aL[mi], &bIFh[nj * 2]);
                        mma_bf16(d[mi][nj + 2], aH[mi], &bGOh[nj * 2]);
                        mma_bf16(d[mi][nj + 2], aH[mi], &bGOl[nj * 2]);
                        mma_bf16(d[mi][nj + 2], aL[mi], &bGOh[nj * 2]);
                    }
            }
            __syncthreads();
            if (c + 2 < 16) {
                fillA(c + 2, s, srcA);
                fillB(c + 2, s, srcB);
            } else if (t < 128) {
                fillB(c - 14, s, srcBn);     // next step's B chunk 0/1 (h-independent)
            }
            CP_COMMIT();
        }

        // ---- epilogue: LSTM cell update (c in regs) + emit next A tile ----
        {
            const int chunk = nT >> 1;
            char* dh = (char*)&g_hbf[t][mT][chunk][0][0];
            char* dl = dh + 16384;
#pragma unroll
            for (int mi = 0; mi < 4; mi++)
#pragma unroll
                for (int rh = 0; rh < 2; rh++) {
                    int bl = wm * 64 + mi * 16 + (lane >> 2) + rh * 8;
#pragma unroll
                    for (int cp = 0; cp < 2; cp++) {
                        int cl = wn * 8 + cp * 4 + (lane & 3);
                        float gi = d[mi][cp][rh * 2 + 0]     + (first ? bZ[cp][0] : bF[cp][0]);
                        float gf = d[mi][cp][rh * 2 + 1]     + (first ? bZ[cp][1] : bF[cp][1]);
                        float gg = d[mi][cp + 2][rh * 2 + 0] + (first ? bZ[cp][2] : bF[cp][2]);
                        float go = d[mi][cp + 2][rh * 2 + 1] + (first ? bZ[cp][3] : bF[cp][3]);
                        float cold = first ? 0.f : creg[mi][rh][cp];
                        float cn = sigm(gf) * cold + sigm(gi) * tanhf(gg);
                        float hn = sigm(go) * tanhf(cn);
                        creg[mi][rh][cp] = cn;
                        __nv_bfloat16 hh, hl; split_w(hn, hh, hl);
                        int kin = (nT & 1) * 32 + cl;
                        u32 off = swz((u32)(bl * 128 + kin * 2));
                        *(__nv_bfloat16*)(dh + off) = hh;
                        *(__nv_bfloat16*)(dl + off) = hl;
                    }
                }
        }

        if (t < 128) {
            __syncthreads();                 // all epilogue STGs issued
            if (tid == 0) {
                asm volatile("fence.release.gpu;" ::: "memory");
                u32* bp = &g_bar[t * 4 + mT];
                asm volatile("red.relaxed.gpu.global.add.u32 [%0], %1;" :: "l"(bp), "r"(1u) : "memory");
                u32 v;
                asm volatile("ld.relaxed.gpu.global.u32 %0, [%1];" : "=r"(v) : "l"(bp) : "memory");
                while (v < 32) {
                    asm volatile("nanosleep.u32 32;");
                    asm volatile("ld.relaxed.gpu.global.u32 %0, [%1];" : "=r"(v) : "l"(bp) : "memory");
                }
                asm volatile("fence.acquire.gpu;" ::: "memory");
            }
            __syncthreads();
            const char* An = (const char*)&g_hbf[t][mT][0][0][0];
            fillA(0, 0, An); CP_COMMIT();
            fillA(1, 1, An); CP_COMMIT();
        }
    }
}

// ---------------- output GEMM: out[b][t][o] = h_{t+1} @ Wout^T + b_out ------
__global__ __launch_bounds__(256, 1) void out_mma(const float* __restrict__ bout,
                                                  float* __restrict__ out)
{
    extern __shared__ char smem[];
    u32 sb = (smem_u32(smem) + 1023) & ~1023u;
    int tid = threadIdx.x, lane = tid & 31, w = tid >> 5;
    int mT = blockIdx.x, nOT = blockIdx.y, t = blockIdx.z;

    const char* srcA = (const char*)&g_hbf[t + 1][mT][0][0][0];
    const char* srcB = (const char*)&g_obf[nOT][0][0][0];

#pragma unroll
    for (int pc = 0; pc < 2; pc++) {
        u32 stg = sb + pc * LSTAGE;
        const char* a = srcA + (size_t)pc * 32768;
        const char* b = srcB + (size_t)pc * 32768;
#pragma unroll
        for (int r = 0; r < 8; r++) { int idx = r * 256 + tid; cpa16(stg + idx * 16, a + (size_t)idx * 16); }
#pragma unroll
        for (int r = 0; r < 8; r++) { int idx = r * 256 + tid; cpa16(stg + 32768 + idx * 16, b + (size_t)idx * 16); }
        CP_COMMIT();
    }

    int wm = w >> 2, wn = w & 3;
    const int aRow = ((lane >> 3) & 1) * 8 + (lane & 7);
    const int aKh  = lane >> 4;
    const int bRow = (lane >> 4) * 8 + (lane & 7);
    const int bKh  = (lane >> 3) & 1;

    float d[4][4][4] = {};

    for (int c = 0; c < 16; c++) {
        int s = c & 1;
        CP_WAIT1();
        __syncthreads();
        u32 stA = sb + s * LSTAGE;
        u32 stB = stA + 32768;
#pragma unroll
        for (int k16 = 0; k16 < 4; k16++) {
            u32 aH[4][4], aL[4][4];
#pragma unroll
            for (int mi = 0; mi < 4; mi++) {
                u32 off = swz((u32)((wm * 64 + mi * 16 + aRow) * 128 + (k16 * 2 + aKh) * 16));
                ldsm4(aH[mi], stA + off);
                ldsm4(aL[mi], stA + 16384 + off);
            }
            u32 bH[2][4], bL[2][4];
#pragma unroll
            for (int bi = 0; bi < 2; bi++) {
                u32 off = swz((u32)((wn * 32 + bi * 16 + bRow) * 128 + (k16 * 2 + bKh) * 16));
                ldsm4(bH[bi], stB + off);
                ldsm4(bL[bi], stB + 16384 + off);
            }
#pragma unroll
            for (int mi = 0; mi < 4; mi++)
#pragma unroll
                for (int nj = 0; nj < 4; nj++) {
                    mma_bf16(d[mi][nj], aH[mi], &bH[nj >> 1][(nj & 1) * 2]);
                    mma_bf16(d[mi][nj], aH[mi], &bL[nj >> 1][(nj & 1) * 2]);
                    mma_bf16(d[mi][nj], aL[mi], &bH[nj >> 1][(nj & 1) * 2]);
                }
        }
        __syncthreads();
        if (c + 2 < 16) {
            u32 stg = sb + s * LSTAGE;
            const char* a = srcA + (size_t)(c + 2) * 32768;
            const char* b = srcB + (size_t)(c + 2) * 32768;
#pragma unroll
            for (int r = 0; r < 8; r++) { int idx = r * 256 + tid; cpa16(stg + idx * 16, a + (size_t)idx * 16); }
#pragma unroll
            for (int r = 0; r < 8; r++) { int idx = r * 256 + tid; cpa16(stg + 32768 + idx * 16, b + (size_t)idx * 16); }
        }
        CP_COMMIT();
    }

#pragma unroll
    for (int mi = 0; mi < 4; mi++)
#pragma unroll
        for (int nj = 0; nj < 4; nj++)
#pragma unroll
            for (int rh = 0; rh < 2; rh++) {
                int bl = wm * 64 + mi * 16 + (lane >> 2) + rh * 8;
                int b = mT * 128 + bl;
                int o = nOT * 128 + wn * 32 + nj * 8 + 2 * (lane & 3);
                float2 v = make_float2(d[mi][nj][rh * 2 + 0] + bout[o],
                                       d[mi][nj][rh * 2 + 1] + bout[o + 1]);
                *(float2*)&out[(size_t)b * 32768 + (size_t)t * 256 + o] = v;
            }
}

// ---------------- launch ----------------
extern "C" void kernel_launch(void* const* d_in, const int* in_sizes, int n_in,
                              void* d_out, int out_size)
{
    const float *enc = nullptr, *Wih = nullptr, *Whh = nullptr;
    const float *bih = nullptr, *bhh = nullptr, *Wout = nullptr, *bout = nullptr;
    for (int i = 0; i < n_in; i++) {
        int s = in_sizes[i];
        if      (s == 512 * 1024)  enc  = (const float*)d_in[i];
        else if (s == 4096 * 256)  Wih  = (const float*)d_in[i];
        else if (s == 4096 * 1024) Whh  = (const float*)d_in[i];
        else if (s == 4096)        { if (!bih) bih = (const float*)d_in[i]; else bhh = (const float*)d_in[i]; }
        else if (s == 256 * 1024)  Wout = (const float*)d_in[i];
        else if (s == 256)         bout = (const float*)d_in[i];
    }
    if (!enc || !Wih || !Whh || !bih || !bhh || !Wout || !bout) return;

    cudaFuncSetAttribute(prep_mma,     cudaFuncAttributeMaxDynamicSharedMemorySize, PREP_SMEM);
    cudaFuncSetAttribute(lstm_persist, cudaFuncAttributeMaxDynamicSharedMemorySize, LSTM_SMEM);
    cudaFuncSetAttribute(out_mma,      cudaFuncAttributeMaxDynamicSharedMemorySize, LSTM_SMEM);

    init_bar<<<3, 256>>>();
    prep_bias<<<512, 256>>>(Wih, bih, bhh, bout);
    conv_w0<<<dim3(16, 32), 256>>>(Whh);
    conv_wih<<<dim3(4, 32), 256>>>(Wih);
    conv_woutT<<<dim3(4, 16), 256>>>(Wout);
    conv_obf<<<dim3(16, 2), 256>>>(Wout);
    conv_h0<<<dim3(16, 4), 256>>>(enc);
    prep_mma<<<dim3(32, 16), 256, PREP_SMEM>>>(Whh);

    lstm_persist<<<dim3(4, 32), 256, LSTM_SMEM>>>();

    out_mma<<<dim3(4, 2, 128), 256, LSTM_SMEM>>>(bout, (float*)d_out);
    (void)out_size;
}

// round 9
// speedup vs baseline: 1.4194x; 1.3313x over previous
#include <cuda_runtime.h>
#include <cuda_bf16.h>
#include <cuda_fp16.h>
#include <cstdint>

typedef unsigned long long ull;
typedef unsigned int u32;

#define HB (1024*512)

// ---------------- scratch (static __device__, no allocations) ----------------
static __device__ float g_b0[4096];               // b_ih+b_hh
static __device__ float g_bf[4096];               // + W_ih@b_out
static __device__ u32   g_bar[516];               // per-(t,mT) arrival counters
// fp16 weight tiles, gate-paired rows, SW128 pre-swizzled: [src][nT 32][chunk 16][part 2][128x64]
static __device__ __align__(256) __half g_wbf[2][32][16][2][8192];
// fp16 hidden tiles: [t 0..128][mT 4][chunk 16][part 2][128x64]
static __device__ __align__(256) __half g_hbf[129][4][16][2][8192];
// fp16 output-weight tiles: [nOT 2][chunk 16][part 2][128x64]
static __device__ __align__(256) __half g_obf[2][16][2][8192];
// prep-GEMM operands (bf16, 3-pass prep path)
static __device__ __align__(256) __nv_bfloat16 g_pA[32][4][2][8192];
static __device__ __align__(256) __nv_bfloat16 g_pB[16][4][2][4096];

// ---------------- helpers ----------------
__device__ __forceinline__ float sigm(float x) { return 1.0f / (1.0f + __expf(-x)); }
__device__ __forceinline__ u32 swz(u32 x) { return x ^ ((x >> 3) & 0x70); }
__device__ __forceinline__ u32 smem_u32(const void* p) {
    u32 a; asm("{ .reg .u64 t; cvta.to.shared.u64 t, %1; cvt.u32.u64 %0, t; }" : "=r"(a) : "l"(p));
    return a;
}
__device__ __forceinline__ void cpa16(u32 dst, const void* src) {
    asm volatile("cp.async.cg.shared.global [%0], [%1], 16;" :: "r"(dst), "l"(src));
}
#define CP_COMMIT() asm volatile("cp.async.commit_group;" ::: "memory")
#define CP_WAIT1()  asm volatile("cp.async.wait_group 1;" ::: "memory")
#define CP_WAIT0()  asm volatile("cp.async.wait_group 0;" ::: "memory")

__device__ __forceinline__ void ldsm4(u32* r, u32 addr) {
    asm volatile("ldmatrix.sync.aligned.m8n8.x4.shared.b16 {%0,%1,%2,%3}, [%4];"
                 : "=r"(r[0]), "=r"(r[1]), "=r"(r[2]), "=r"(r[3]) : "r"(addr));
}
__device__ __forceinline__ void mma_bf16(float* d, const u32* a, const u32* b) {
    asm volatile("mma.sync.aligned.m16n8k16.row.col.f32.bf16.bf16.f32 "
                 "{%0,%1,%2,%3}, {%4,%5,%6,%7}, {%8,%9}, {%0,%1,%2,%3};"
                 : "+f"(d[0]), "+f"(d[1]), "+f"(d[2]), "+f"(d[3])
                 : "r"(a[0]), "r"(a[1]), "r"(a[2]), "r"(a[3]), "r"(b[0]), "r"(b[1]));
}
__device__ __forceinline__ void mma_f16(float* d, const u32* a, const u32* b) {
    asm volatile("mma.sync.aligned.m16n8k16.row.col.f32.f16.f16.f32 "
                 "{%0,%1,%2,%3}, {%4,%5,%6,%7}, {%8,%9}, {%0,%1,%2,%3};"
                 : "+f"(d[0]), "+f"(d[1]), "+f"(d[2]), "+f"(d[3])
                 : "r"(a[0]), "r"(a[1]), "r"(a[2]), "r"(a[3]), "r"(b[0]), "r"(b[1]));
}
__device__ __forceinline__ void split_h16(float v, __half& h, __half& l) {
    h = __float2half_rn(v);
    l = __float2half_rn(v - __half2float(h));
}
__device__ __forceinline__ u32 pack_split2h(float v0, float v1, u32& lo_out) {
    __half h0, l0, h1, l1;
    split_h16(v0, h0, l0); split_h16(v1, h1, l1);
    lo_out = (u32)__half_as_ushort(l0) | ((u32)__half_as_ushort(l1) << 16);
    return (u32)__half_as_ushort(h0) | ((u32)__half_as_ushort(h1) << 16);
}
__device__ __forceinline__ void split_bf(float v, __nv_bfloat16& h, __nv_bfloat16& l) {
    h = __float2bfloat16(v);
    l = __float2bfloat16(v - __bfloat162float(h));
}
// gate-paired row -> j (j = gate*1024 + cell)
__device__ __forceinline__ int rowj(int nT, int n) {
    int half = n >> 6, m = n & 63;
    return (half * 2 + (m & 1)) * 1024 + nT * 32 + (m >> 1);
}

// ---------------- init barrier counters ----------------
__global__ void init_bar() {
    int i = blockIdx.x * 256 + threadIdx.x;
    if (i < 516) g_bar[i] = 0;
}

// ---------------- prep: biases (warp per j) ----------------
__global__ void prep_bias(const float* __restrict__ Wih, const float* __restrict__ bih,
                          const float* __restrict__ bhh, const float* __restrict__ bout)
{
    int w = threadIdx.x >> 5, lane = threadIdx.x & 31;
    int j = blockIdx.x * 8 + w;
    float acc = 0.f;
#pragma unroll
    for (int i = 0; i < 8; i++) acc += Wih[(size_t)j * 256 + i * 32 + lane] * bout[i * 32 + lane];
#pragma unroll
    for (int o = 16; o; o >>= 1) acc += __shfl_xor_sync(0xFFFFFFFFu, acc, o);
    if (lane == 0) {
        float s = bih[j] + bhh[j];
        g_b0[j] = s;
        g_bf[j] = s + acc;
    }
}

// ---------------- conv: Whh -> g_wbf[0] (fp16 split, coalesced) ----------------
__global__ void conv_w0(const float* __restrict__ Whh)
{
    int chunk = blockIdx.x, nT = blockIdx.y;
    int w = threadIdx.x >> 5, lane = threadIdx.x & 31;
    char* th = (char*)&g_wbf[0][nT][chunk][0][0];
    char* tl = th + 16384;
#pragma unroll
    for (int r = 0; r < 16; r++) {
        int n = r * 8 + w;
        const float2 v2 = *(const float2*)&Whh[(size_t)rowj(nT, n) * 1024 + chunk * 64 + lane * 2];
        u32 lo, hi = pack_split2h(v2.x, v2.y, lo);
        u32 off = swz((u32)(n * 128 + lane * 4));
        *(u32*)(th + off) = hi;
        *(u32*)(tl + off) = lo;
    }
}

// ---------------- conv: Wih -> g_pA (bf16, prep path) ----------------
__global__ void conv_wih(const float* __restrict__ Wih)
{
    int oc = blockIdx.x, nT = blockIdx.y;
    int w = threadIdx.x >> 5, lane = threadIdx.x & 31;
    char* th = (char*)&g_pA[nT][oc][0][0];
    char* tl = th + 16384;
#pragma unroll
    for (int r = 0; r < 16; r++) {
        int n = r * 8 + w;
        const float2 v2 = *(const float2*)&Wih[(size_t)rowj(nT, n) * 256 + oc * 64 + lane * 2];
        __nv_bfloat16 h0, l0, h1, l1;
        split_bf(v2.x, h0, l0); split_bf(v2.y, h1, l1);
        u32 hi = (u32)__bfloat16_as_ushort(h0) | ((u32)__bfloat16_as_ushort(h1) << 16);
        u32 lo = (u32)__bfloat16_as_ushort(l0) | ((u32)__bfloat16_as_ushort(l1) << 16);
        u32 off = swz((u32)(n * 128 + lane * 4));
        *(u32*)(th + off) = hi;
        *(u32*)(tl + off) = lo;
    }
}

// ---------------- conv: Wout^T -> g_pB (bf16, prep path) ----------------
__global__ void conv_woutT(const float* __restrict__ Wout)
{
    int oc = blockIdx.x, kc = blockIdx.y;
    int k = threadIdx.x & 63, og = threadIdx.x >> 6;
    char* th = (char*)&g_pB[kc][oc][0][0];
    char* tl = th + 8192;
#pragma unroll
    for (int i = 0; i < 16; i++) {
        int oo = og * 16 + i;
        float v = Wout[(size_t)(oc * 64 + oo) * 1024 + kc * 64 + k];
        __nv_bfloat16 h, l; split_bf(v, h, l);
        u32 off = swz((u32)(k * 128 + oo * 2));
        *(__nv_bfloat16*)(th + off) = h;
        *(__nv_bfloat16*)(tl + off) = l;
    }
}

// ---------------- conv: Wout -> g_obf (fp16 split) ----------------
__global__ void conv_obf(const float* __restrict__ Wout)
{
    int chunk = blockIdx.x, nOT = blockIdx.y;
    int w = threadIdx.x >> 5, lane = threadIdx.x & 31;
    char* th = (char*)&g_obf[nOT][chunk][0][0];
    char* tl = th + 16384;
#pragma unroll
    for (int r = 0; r < 16; r++) {
        int n = r * 8 + w;
        const float2 v2 = *(const float2*)&Wout[(size_t)(nOT * 128 + n) * 1024 + chunk * 64 + lane * 2];
        u32 lo, hi = pack_split2h(v2.x, v2.y, lo);
        u32 off = swz((u32)(n * 128 + lane * 4));
        *(u32*)(th + off) = hi;
        *(u32*)(tl + off) = lo;
    }
}

// ---------------- conv: encoder h0 -> g_hbf[0] (fp16 split) ----------------
__global__ void conv_h0(const float* __restrict__ enc)
{
    int chunk = blockIdx.x, mT = blockIdx.y;
    int w = threadIdx.x >> 5, lane = threadIdx.x & 31;
    char* th = (char*)&g_hbf[0][mT][chunk][0][0];
    char* tl = th + 16384;
#pragma unroll
    for (int r = 0; r < 16; r++) {
        int m = r * 8 + w;
        const float2 v2 = *(const float2*)&enc[(size_t)(mT * 128 + m) * 1024 + chunk * 64 + lane * 2];
        u32 lo, hi = pack_split2h(v2.x, v2.y, lo);
        u32 off = swz((u32)(m * 128 + lane * 4));
        *(u32*)(th + off) = hi;
        *(u32*)(tl + off) = lo;
    }
}

// ---------------- prep GEMM: g_wbf[1] = fp16split(Whh + Wih @ Wout^T), bf16 3-pass ----
#define PREP_SMEM (128*1024 + 64*1024 + 1024)
__global__ __launch_bounds__(256, 1) void prep_mma(const float* __restrict__ Whh)
{
    extern __shared__ char smem[];
    u32 sb = (smem_u32(smem) + 1023) & ~1023u;
    int tid = threadIdx.x, lane = tid & 31, w = tid >> 5;
    int nT = blockIdx.x, kc = blockIdx.y;

    const char* srcA = (const char*)&g_pA[nT][0][0][0];
    const char* srcB = (const char*)&g_pB[kc][0][0][0];
#pragma unroll
    for (int r = 0; r < 32; r++) { int idx = r * 256 + tid; cpa16(sb + idx * 16, srcA + (size_t)idx * 16); }
#pragma unroll
    for (int r = 0; r < 16; r++) { int idx = r * 256 + tid; cpa16(sb + 131072 + idx * 16, srcB + (size_t)idx * 16); }
    CP_COMMIT(); CP_WAIT0();
    __syncthreads();

    int wm = w >> 1, wn = w & 1;
    const int aRow = ((lane >> 3) & 1) * 8 + (lane & 7);
    const int aKh  = lane >> 4;
    const int bRow = (lane >> 4) * 8 + (lane & 7);
    const int bKh  = (lane >> 3) & 1;

    float d[2][4][4] = {};
#pragma unroll
    for (int oc = 0; oc < 4; oc++) {
        u32 stA = sb + oc * 32768;
        u32 stB = sb + 131072 + oc * 16384;
#pragma unroll
        for (int k16 = 0; k16 < 4; k16++) {
            u32 aH[2][4], aL[2][4];
#pragma unroll
            for (int mi = 0; mi < 2; mi++) {
                u32 off = swz((u32)((wm * 32 + mi * 16 + aRow) * 128 + (k16 * 2 + aKh) * 16));
                ldsm4(aH[mi], stA + off);
                ldsm4(aL[mi], stA + 16384 + off);
            }
            u32 bH[2][4], bL[2][4];
#pragma unroll
            for (int bi = 0; bi < 2; bi++) {
                u32 off = swz((u32)((wn * 32 + bi * 16 + bRow) * 128 + (k16 * 2 + bKh) * 16));
                ldsm4(bH[bi], stB + off);
                ldsm4(bL[bi], stB + 8192 + off);
            }
#pragma unroll
            for (int mi = 0; mi < 2; mi++)
#pragma unroll
                for (int nj = 0; nj < 4; nj++) {
                    mma_bf16(d[mi][nj], aH[mi], &bH[nj >> 1][(nj & 1) * 2]);
                    mma_bf16(d[mi][nj], aH[mi], &bL[nj >> 1][(nj & 1) * 2]);
                    mma_bf16(d[mi][nj], aL[mi], &bH[nj >> 1][(nj & 1) * 2]);
                }
        }
    }

    char* th = (char*)&g_wbf[1][nT][kc][0][0];
    char* tl = th + 16384;
#pragma unroll
    for (int mi = 0; mi < 2; mi++)
#pragma unroll
        for (int nj = 0; nj < 4; nj++)
#pragma unroll
            for (int rh = 0; rh < 2; rh++) {
                int n = wm * 32 + mi * 16 + (lane >> 2) + rh * 8;
                int j = rowj(nT, n);
                int k0l = wn * 32 + nj * 8 + 2 * (lane & 3);
                const float* wr = Whh + (size_t)j * 1024 + kc * 64 + k0l;
                u32 lo, hi = pack_split2h(d[mi][nj][rh * 2 + 0] + wr[0],
                                          d[mi][nj][rh * 2 + 1] + wr[1], lo);
                u32 off = swz((u32)(n * 128 + k0l * 2));
                *(u32*)(th + off) = hi;
                *(u32*)(tl + off) = lo;
            }
}

// ---------------- persistent LSTM: fp16 2-pass (A hi-only, B split) ----------------
// grid (4 mT, 32 nT) = 128 CTAs resident. Stage = A hi 16KB + B 32KB = 48KB, 2 stages.
#define LSTAGE 49152
#define LSTM_SMEM (2*LSTAGE + 1024)
__global__ __launch_bounds__(256, 1) void lstm_persist()
{
    extern __shared__ char smem[];
    u32 sb = (smem_u32(smem) + 1023) & ~1023u;
    const int tid = threadIdx.x, lane = tid & 31, w = tid >> 5;
    const int mT = blockIdx.x, nT = blockIdx.y;
    const int wm = w >> 2, wn = w & 3;
    const int aRow = ((lane >> 3) & 1) * 8 + (lane & 7);
    const int aKh  = lane >> 4;
    const int bRow = (lane >> 4) * 8 + (lane & 7);
    const int bKh  = (lane >> 3) & 1;

    // A: only hi part (16KB of the 32KB chunk)
    auto fillA = [&](int c, int s, const char* src) {
#pragma unroll
        for (int r = 0; r < 4; r++) {
            int idx = r * 256 + tid;
            cpa16(sb + s * LSTAGE + idx * 16, src + (size_t)c * 32768 + idx * 16);
        }
    };
    // B: both parts (32KB)
    auto fillB = [&](int c, int s, const char* src) {
#pragma unroll
        for (int r = 0; r < 8; r++) {
            int idx = r * 256 + tid;
            cpa16(sb + s * LSTAGE + 16384 + idx * 16, src + (size_t)c * 32768 + idx * 16);
        }
    };

    float bZ[2][4], bF[2][4];
#pragma unroll
    for (int cp = 0; cp < 2; cp++) {
        int cell = nT * 32 + wn * 8 + cp * 4 + (lane & 3);
#pragma unroll
        for (int g = 0; g < 4; g++) {
            bZ[cp][g] = g_b0[g * 1024 + cell];
            bF[cp][g] = g_bf[g * 1024 + cell];
        }
    }

    float creg[4][2][2];
#pragma unroll
    for (int mi = 0; mi < 4; mi++)
#pragma unroll
        for (int rh = 0; rh < 2; rh++)
#pragma unroll
            for (int cp = 0; cp < 2; cp++) creg[mi][rh][cp] = 0.f;

    const char* srcBn = (const char*)&g_wbf[1][nT][0][0][0];

    // prologue: B0,B1,A0,A1 as 4 groups (order matters for wait_group 1)
    {
        const char* B1 = (const char*)&g_wbf[0][nT][0][0][0];
        const char* A1 = (const char*)&g_hbf[0][mT][0][0][0];
        fillB(0, 0, B1); CP_COMMIT();
        fillB(1, 1, B1); CP_COMMIT();
        fillA(0, 0, A1); CP_COMMIT();
        fillA(1, 1, A1); CP_COMMIT();
    }

    for (int t = 1; t <= 128; t++) {
        const int first = (t == 1);
        const char* srcA = (const char*)&g_hbf[t - 1][mT][0][0][0];
        const char* srcB = first ? (const char*)&g_wbf[0][nT][0][0][0] : srcBn;

        float d[4][4][4];
#pragma unroll
        for (int mi = 0; mi < 4; mi++)
#pragma unroll
            for (int nj = 0; nj < 4; nj++)
#pragma unroll
                for (int q = 0; q < 4; q++) d[mi][nj][q] = 0.f;

        for (int c = 0; c < 16; c++) {
            int s = c & 1;
            CP_WAIT1();
            __syncthreads();
            u32 stA = sb + s * LSTAGE;
            u32 stB = stA + 16384;
#pragma unroll
            for (int k16 = 0; k16 < 4; k16++) {
                u32 aH[4][4];
#pragma unroll
                for (int mi = 0; mi < 4; mi++) {
                    u32 off = swz((u32)((wm * 64 + mi * 16 + aRow) * 128 + (k16 * 2 + aKh) * 16));
                    ldsm4(aH[mi], stA + off);
                }
                u32 bIFh[4], bIFl[4], bGOh[4], bGOl[4];
                {
                    u32 offIF = swz((u32)((wn * 16 + bRow) * 128 + (k16 * 2 + bKh) * 16));
                    u32 offGO = swz((u32)((64 + wn * 16 + bRow) * 128 + (k16 * 2 + bKh) * 16));
                    ldsm4(bIFh, stB + offIF); ldsm4(bIFl, stB + 16384 + offIF);
                    ldsm4(bGOh, stB + offGO); ldsm4(bGOl, stB + 16384 + offGO);
                }
#pragma unroll
                for (int mi = 0; mi < 4; mi++)
#pragma unroll
                    for (int nj = 0; nj < 2; nj++) {
                        mma_f16(d[mi][nj],     aH[mi], &bIFh[nj * 2]);
                        mma_f16(d[mi][nj],     aH[mi], &bIFl[nj * 2]);
                        mma_f16(d[mi][nj + 2], aH[mi], &bGOh[nj * 2]);
                        mma_f16(d[mi][nj + 2], aH[mi], &bGOl[nj * 2]);
                    }
            }
            __syncthreads();
            if (c + 2 < 16) {
                fillA(c + 2, s, srcA);
                fillB(c + 2, s, srcB);
            } else if (t < 128) {
                fillB(c - 14, s, srcBn);     // next step's B chunk 0/1 (h-independent)
            }
            CP_COMMIT();
        }

        // ---- epilogue: LSTM cell update (c in regs) + emit next A tile (fp16 split) ----
        {
            const int chunk = nT >> 1;
            char* dh = (char*)&g_hbf[t][mT][chunk][0][0];
            char* dl = dh + 16384;
#pragma unroll
            for (int mi = 0; mi < 4; mi++)
#pragma unroll
                for (int rh = 0; rh < 2; rh++) {
                    int bl = wm * 64 + mi * 16 + (lane >> 2) + rh * 8;
#pragma unroll
                    for (int cp = 0; cp < 2; cp++) {
                        int cl = wn * 8 + cp * 4 + (lane & 3);
                        float gi = d[mi][cp][rh * 2 + 0]     + (first ? bZ[cp][0] : bF[cp][0]);
                        float gf = d[mi][cp][rh * 2 + 1]     + (first ? bZ[cp][1] : bF[cp][1]);
                        float gg = d[mi][cp + 2][rh * 2 + 0] + (first ? bZ[cp][2] : bF[cp][2]);
                        float go = d[mi][cp + 2][rh * 2 + 1] + (first ? bZ[cp][3] : bF[cp][3]);
                        float cold = first ? 0.f : creg[mi][rh][cp];
                        float cn = sigm(gf) * cold + sigm(gi) * tanhf(gg);
                        float hn = sigm(go) * tanhf(cn);
                        creg[mi][rh][cp] = cn;
                        __half hh, hl; split_h16(hn, hh, hl);
                        int kin = (nT & 1) * 32 + cl;
                        u32 off = swz((u32)(bl * 128 + kin * 2));
                        *(__half*)(dh + off) = hh;
                        *(__half*)(dl + off) = hl;
                    }
                }
        }

        if (t < 128) {
            __syncthreads();                 // all epilogue STGs issued
            if (tid == 0) {
                asm volatile("fence.release.gpu;" ::: "memory");
                u32* bp = &g_bar[t * 4 + mT];
                asm volatile("red.relaxed.gpu.global.add.u32 [%0], %1;" :: "l"(bp), "r"(1u) : "memory");
                u32 v;
                asm volatile("ld.relaxed.gpu.global.u32 %0, [%1];" : "=r"(v) : "l"(bp) : "memory");
                while (v < 32) {
                    asm volatile("nanosleep.u32 32;");
                    asm volatile("ld.relaxed.gpu.global.u32 %0, [%1];" : "=r"(v) : "l"(bp) : "memory");
                }
                asm volatile("fence.acquire.gpu;" ::: "memory");
            }
            __syncthreads();
            const char* An = (const char*)&g_hbf[t][mT][0][0][0];
            fillA(0, 0, An); CP_COMMIT();
            fillA(1, 1, An); CP_COMMIT();
        }
    }
}

// ---------------- output GEMM: fp16 3-pass, out[b][t][o] = h_{t+1} @ Wout^T + b_out ----
#define OSTAGE 65536
#define OUT_SMEM (2*OSTAGE + 1024)
__global__ __launch_bounds__(256, 1) void out_mma(const float* __restrict__ bout,
                                                  float* __restrict__ out)
{
    extern __shared__ char smem[];
    u32 sb = (smem_u32(smem) + 1023) & ~1023u;
    int tid = threadIdx.x, lane = tid & 31, w = tid >> 5;
    int mT = blockIdx.x, nOT = blockIdx.y, t = blockIdx.z;

    const char* srcA = (const char*)&g_hbf[t + 1][mT][0][0][0];
    const char* srcB = (const char*)&g_obf[nOT][0][0][0];

#pragma unroll
    for (int pc = 0; pc < 2; pc++) {
        u32 stg = sb + pc * OSTAGE;
        const char* a = srcA + (size_t)pc * 32768;
        const char* b = srcB + (size_t)pc * 32768;
#pragma unroll
        for (int r = 0; r < 8; r++) { int idx = r * 256 + tid; cpa16(stg + idx * 16, a + (size_t)idx * 16); }
#pragma unroll
        for (int r = 0; r < 8; r++) { int idx = r * 256 + tid; cpa16(stg + 32768 + idx * 16, b + (size_t)idx * 16); }
        CP_COMMIT();
    }

    int wm = w >> 2, wn = w & 3;
    const int aRow = ((lane >> 3) & 1) * 8 + (lane & 7);
    const int aKh  = lane >> 4;
    const int bRow = (lane >> 4) * 8 + (lane & 7);
    const int bKh  = (lane >> 3) & 1;

    float d[4][4][4] = {};

    for (int c = 0; c < 16; c++) {
        int s = c & 1;
        CP_WAIT1();
        __syncthreads();
        u32 stA = sb + s * OSTAGE;
        u32 stB = stA + 32768;
#pragma unroll
        for (int k16 = 0; k16 < 4; k16++) {
            u32 aH[4][4], aL[4][4];
#pragma unroll
            for (int mi = 0; mi < 4; mi++) {
                u32 off = swz((u32)((wm * 64 + mi * 16 + aRow) * 128 + (k16 * 2 + aKh) * 16));
                ldsm4(aH[mi], stA + off);
                ldsm4(aL[mi], stA + 16384 + off);
            }
            u32 bH[2][4], bL[2][4];
#pragma unroll
            for (int bi = 0; bi < 2; bi++) {
                u32 off = swz((u32)((wn * 32 + bi * 16 + bRow) * 128 + (k16 * 2 + bKh) * 16));
                ldsm4(bH[bi], stB + off);
                ldsm4(bL[bi], stB + 16384 + off);
            }
#pragma unroll
            for (int mi = 0; mi < 4; mi++)
#pragma unroll
                for (int nj = 0; nj < 4; nj++) {
                    mma_f16(d[mi][nj], aH[mi], &bH[nj >> 1][(nj & 1) * 2]);
                    mma_f16(d[mi][nj], aH[mi], &bL[nj >> 1][(nj & 1) * 2]);
                    mma_f16(d[mi][nj], aL[mi], &bH[nj >> 1][(nj & 1) * 2]);
                }
        }
        __syncthreads();
        if (c + 2 < 16) {
            u32 stg = sb + s * OSTAGE;
            const char* a = srcA + (size_t)(c + 2) * 32768;
            const char* b = srcB + (size_t)(c + 2) * 32768;
#pragma unroll
            for (int r = 0; r < 8; r++) { int idx = r * 256 + tid; cpa16(stg + idx * 16, a + (size_t)idx * 16); }
#pragma unroll
            for (int r = 0; r < 8; r++) { int idx = r * 256 + tid; cpa16(stg + 32768 + idx * 16, b + (size_t)idx * 16); }
        }
        CP_COMMIT();
    }

#pragma unroll
    for (int mi = 0; mi < 4; mi++)
#pragma unroll
        for (int nj = 0; nj < 4; nj++)
#pragma unroll
            for (int rh = 0; rh < 2; rh++) {
                int bl = wm * 64 + mi * 16 + (lane >> 2) + rh * 8;
                int b = mT * 128 + bl;
                int o = nOT * 128 + wn * 32 + nj * 8 + 2 * (lane & 3);
                float2 v = make_float2(d[mi][nj][rh * 2 + 0] + bout[o],
                                       d[mi][nj][rh * 2 + 1] + bout[o + 1]);
                *(float2*)&out[(size_t)b * 32768 + (size_t)t * 256 + o] = v;
            }
}

// ---------------- launch ----------------
extern "C" void kernel_launch(void* const* d_in, const int* in_sizes, int n_in,
                              void* d_out, int out_size)
{
    const float *enc = nullptr, *Wih = nullptr, *Whh = nullptr;
    const float *bih = nullptr, *bhh = nullptr, *Wout = nullptr, *bout = nullptr;
    for (int i = 0; i < n_in; i++) {
        int s = in_sizes[i];
        if      (s == 512 * 1024)  enc  = (const float*)d_in[i];
        else if (s == 4096 * 256)  Wih  = (const float*)d_in[i];
        else if (s == 4096 * 1024) Whh  = (const float*)d_in[i];
        else if (s == 4096)        { if (!bih) bih = (const float*)d_in[i]; else bhh = (const float*)d_in[i]; }
        else if (s == 256 * 1024)  Wout = (const float*)d_in[i];
        else if (s == 256)         bout = (const float*)d_in[i];
    }
    if (!enc || !Wih || !Whh || !bih || !bhh || !Wout || !bout) return;

    cudaFuncSetAttribute(prep_mma,     cudaFuncAttributeMaxDynamicSharedMemorySize, PREP_SMEM);
    cudaFuncSetAttribute(lstm_persist, cudaFuncAttributeMaxDynamicSharedMemorySize, LSTM_SMEM);
    cudaFuncSetAttribute(out_mma,      cudaFuncAttributeMaxDynamicSharedMemorySize, OUT_SMEM);

    init_bar<<<3, 256>>>();
    prep_bias<<<512, 256>>>(Wih, bih, bhh, bout);
    conv_w0<<<dim3(16, 32), 256>>>(Whh);
    conv_wih<<<dim3(4, 32), 256>>>(Wih);
    conv_woutT<<<dim3(4, 16), 256>>>(Wout);
    conv_obf<<<dim3(16, 2), 256>>>(Wout);
    conv_h0<<<dim3(16, 4), 256>>>(enc);
    prep_mma<<<dim3(32, 16), 256, PREP_SMEM>>>(Whh);

    lstm_persist<<<dim3(4, 32), 256, LSTM_SMEM>>>();

    out_mma<<<dim3(4, 2, 128), 256, OUT_SMEM>>>(bout, (float*)d_out);
    (void)out_size;
}

// round 10
// speedup vs baseline: 2.1713x; 1.5297x over previous
#include <cuda_runtime.h>
#include <cuda_bf16.h>
#include <cuda_fp16.h>
#include <cstdint>

typedef unsigned long long ull;
typedef unsigned int u32;

// ---------------- scratch (static __device__, no allocations) ----------------
static __device__ float g_b0[4096];               // b_ih+b_hh
static __device__ float g_bf[4096];               // + W_ih@b_out
static __device__ u32   g_bar[516];               // per-(t,mT) arrival counters
// fp16 HI-ONLY weight tiles, gate-paired rows, SW128: [src][nT 32][chunk 16][128x64]
static __device__ __align__(256) __half g_wbf[2][32][16][8192];
// fp16 HI-ONLY hidden tiles: [t 0..128][mT 4][chunk 16][128x64]
static __device__ __align__(256) __half g_hbf[129][4][16][8192];
// fp16 SPLIT output-weight tiles: [nOT 2][chunk 16][part 2][128x64]
static __device__ __align__(256) __half g_obf[2][16][2][8192];
// prep-GEMM operands (bf16 split, 3-pass prep path)
static __device__ __align__(256) __nv_bfloat16 g_pA[32][4][2][8192];
static __device__ __align__(256) __nv_bfloat16 g_pB[16][4][2][4096];

// ---------------- helpers ----------------
__device__ __forceinline__ float sigm(float x) { return 1.0f / (1.0f + __expf(-x)); }
__device__ __forceinline__ u32 swz(u32 x) { return x ^ ((x >> 3) & 0x70); }
__device__ __forceinline__ u32 smem_u32(const void* p) {
    u32 a; asm("{ .reg .u64 t; cvta.to.shared.u64 t, %1; cvt.u32.u64 %0, t; }" : "=r"(a) : "l"(p));
    return a;
}
__device__ __forceinline__ void cpa16(u32 dst, const void* src) {
    asm volatile("cp.async.cg.shared.global [%0], [%1], 16;" :: "r"(dst), "l"(src));
}
#define CP_COMMIT() asm volatile("cp.async.commit_group;" ::: "memory")
#define CP_WAIT1()  asm volatile("cp.async.wait_group 1;" ::: "memory")
#define CP_WAIT0()  asm volatile("cp.async.wait_group 0;" ::: "memory")

__device__ __forceinline__ void ldsm4(u32* r, u32 addr) {
    asm volatile("ldmatrix.sync.aligned.m8n8.x4.shared.b16 {%0,%1,%2,%3}, [%4];"
                 : "=r"(r[0]), "=r"(r[1]), "=r"(r[2]), "=r"(r[3]) : "r"(addr));
}
__device__ __forceinline__ void mma_bf16(float* d, const u32* a, const u32* b) {
    asm volatile("mma.sync.aligned.m16n8k16.row.col.f32.bf16.bf16.f32 "
                 "{%0,%1,%2,%3}, {%4,%5,%6,%7}, {%8,%9}, {%0,%1,%2,%3};"
                 : "+f"(d[0]), "+f"(d[1]), "+f"(d[2]), "+f"(d[3])
                 : "r"(a[0]), "r"(a[1]), "r"(a[2]), "r"(a[3]), "r"(b[0]), "r"(b[1]));
}
__device__ __forceinline__ void mma_f16(float* d, const u32* a, const u32* b) {
    asm volatile("mma.sync.aligned.m16n8k16.row.col.f32.f16.f16.f32 "
                 "{%0,%1,%2,%3}, {%4,%5,%6,%7}, {%8,%9}, {%0,%1,%2,%3};"
                 : "+f"(d[0]), "+f"(d[1]), "+f"(d[2]), "+f"(d[3])
                 : "r"(a[0]), "r"(a[1]), "r"(a[2]), "r"(a[3]), "r"(b[0]), "r"(b[1]));
}
__device__ __forceinline__ void split_h16(float v, __half& h, __half& l) {
    h = __float2half_rn(v);
    l = __float2half_rn(v - __half2float(h));
}
__device__ __forceinline__ u32 pack2h(float v0, float v1) {
    __half h0 = __float2half_rn(v0), h1 = __float2half_rn(v1);
    return (u32)__half_as_ushort(h0) | ((u32)__half_as_ushort(h1) << 16);
}
__device__ __forceinline__ u32 pack_split2h(float v0, float v1, u32& lo_out) {
    __half h0, l0, h1, l1;
    split_h16(v0, h0, l0); split_h16(v1, h1, l1);
    lo_out = (u32)__half_as_ushort(l0) | ((u32)__half_as_ushort(l1) << 16);
    return (u32)__half_as_ushort(h0) | ((u32)__half_as_ushort(h1) << 16);
}
__device__ __forceinline__ void split_bf(float v, __nv_bfloat16& h, __nv_bfloat16& l) {
    h = __float2bfloat16(v);
    l = __float2bfloat16(v - __bfloat162float(h));
}
// gate-paired row -> j (j = gate*1024 + cell)
__device__ __forceinline__ int rowj(int nT, int n) {
    int half = n >> 6, m = n & 63;
    return (half * 2 + (m & 1)) * 1024 + nT * 32 + (m >> 1);
}

// ---------------- init barrier counters ----------------
__global__ void init_bar() {
    int i = blockIdx.x * 256 + threadIdx.x;
    if (i < 516) g_bar[i] = 0;
}

// ---------------- prep: biases (warp per j) ----------------
__global__ void prep_bias(const float* __restrict__ Wih, const float* __restrict__ bih,
                          const float* __restrict__ bhh, const float* __restrict__ bout)
{
    int w = threadIdx.x >> 5, lane = threadIdx.x & 31;
    int j = blockIdx.x * 8 + w;
    float acc = 0.f;
#pragma unroll
    for (int i = 0; i < 8; i++) acc += Wih[(size_t)j * 256 + i * 32 + lane] * bout[i * 32 + lane];
#pragma unroll
    for (int o = 16; o; o >>= 1) acc += __shfl_xor_sync(0xFFFFFFFFu, acc, o);
    if (lane == 0) {
        float s = bih[j] + bhh[j];
        g_b0[j] = s;
        g_bf[j] = s + acc;
    }
}

// ---------------- conv: Whh -> g_wbf[0] (fp16 hi-only, coalesced) ----------------
__global__ void conv_w0(const float* __restrict__ Whh)
{
    int chunk = blockIdx.x, nT = blockIdx.y;
    int w = threadIdx.x >> 5, lane = threadIdx.x & 31;
    char* th = (char*)&g_wbf[0][nT][chunk][0];
#pragma unroll
    for (int r = 0; r < 16; r++) {
        int n = r * 8 + w;
        const float2 v2 = *(const float2*)&Whh[(size_t)rowj(nT, n) * 1024 + chunk * 64 + lane * 2];
        u32 off = swz((u32)(n * 128 + lane * 4));
        *(u32*)(th + off) = pack2h(v2.x, v2.y);
    }
}

// ---------------- conv: Wih -> g_pA (bf16 split, prep path) ----------------
__global__ void conv_wih(const float* __restrict__ Wih)
{
    int oc = blockIdx.x, nT = blockIdx.y;
    int w = threadIdx.x >> 5, lane = threadIdx.x & 31;
    char* th = (char*)&g_pA[nT][oc][0][0];
    char* tl = th + 16384;
#pragma unroll
    for (int r = 0; r < 16; r++) {
        int n = r * 8 + w;
        const float2 v2 = *(const float2*)&Wih[(size_t)rowj(nT, n) * 256 + oc * 64 + lane * 2];
        __nv_bfloat16 h0, l0, h1, l1;
        split_bf(v2.x, h0, l0); split_bf(v2.y, h1, l1);
        u32 hi = (u32)__bfloat16_as_ushort(h0) | ((u32)__bfloat16_as_ushort(h1) << 16);
        u32 lo = (u32)__bfloat16_as_ushort(l0) | ((u32)__bfloat16_as_ushort(l1) << 16);
        u32 off = swz((u32)(n * 128 + lane * 4));
        *(u32*)(th + off) = hi;
        *(u32*)(tl + off) = lo;
    }
}

// ---------------- conv: Wout^T -> g_pB (bf16 split, prep path) ----------------
__global__ void conv_woutT(const float* __restrict__ Wout)
{
    int oc = blockIdx.x, kc = blockIdx.y;
    int k = threadIdx.x & 63, og = threadIdx.x >> 6;
    char* th = (char*)&g_pB[kc][oc][0][0];
    char* tl = th + 8192;
#pragma unroll
    for (int i = 0; i < 16; i++) {
        int oo = og * 16 + i;
        float v = Wout[(size_t)(oc * 64 + oo) * 1024 + kc * 64 + k];
        __nv_bfloat16 h, l; split_bf(v, h, l);
        u32 off = swz((u32)(k * 128 + oo * 2));
        *(__nv_bfloat16*)(th + off) = h;
        *(__nv_bfloat16*)(tl + off) = l;
    }
}

// ---------------- conv: Wout -> g_obf (fp16 split) ----------------
__global__ void conv_obf(const float* __restrict__ Wout)
{
    int chunk = blockIdx.x, nOT = blockIdx.y;
    int w = threadIdx.x >> 5, lane = threadIdx.x & 31;
    char* th = (char*)&g_obf[nOT][chunk][0][0];
    char* tl = th + 16384;
#pragma unroll
    for (int r = 0; r < 16; r++) {
        int n = r * 8 + w;
        const float2 v2 = *(const float2*)&Wout[(size_t)(nOT * 128 + n) * 1024 + chunk * 64 + lane * 2];
        u32 lo, hi = pack_split2h(v2.x, v2.y, lo);
        u32 off = swz((u32)(n * 128 + lane * 4));
        *(u32*)(th + off) = hi;
        *(u32*)(tl + off) = lo;
    }
}

// ---------------- conv: encoder h0 -> g_hbf[0] (fp16 hi-only) ----------------
__global__ void conv_h0(const float* __restrict__ enc)
{
    int chunk = blockIdx.x, mT = blockIdx.y;
    int w = threadIdx.x >> 5, lane = threadIdx.x & 31;
    char* th = (char*)&g_hbf[0][mT][chunk][0];
#pragma unroll
    for (int r = 0; r < 16; r++) {
        int m = r * 8 + w;
        const float2 v2 = *(const float2*)&enc[(size_t)(mT * 128 + m) * 1024 + chunk * 64 + lane * 2];
        u32 off = swz((u32)(m * 128 + lane * 4));
        *(u32*)(th + off) = pack2h(v2.x, v2.y);
    }
}

// ---------------- prep GEMM: g_wbf[1] = fp16(Whh + Wih @ Wout^T), bf16 3-pass -------
#define PREP_SMEM (128*1024 + 64*1024 + 1024)
__global__ __launch_bounds__(256, 1) void prep_mma(const float* __restrict__ Whh)
{
    extern __shared__ char smem[];
    u32 sb = (smem_u32(smem) + 1023) & ~1023u;
    int tid = threadIdx.x, lane = tid & 31, w = tid >> 5;
    int nT = blockIdx.x, kc = blockIdx.y;

    const char* srcA = (const char*)&g_pA[nT][0][0][0];
    const char* srcB = (const char*)&g_pB[kc][0][0][0];
#pragma unroll
    for (int r = 0; r < 32; r++) { int idx = r * 256 + tid; cpa16(sb + idx * 16, srcA + (size_t)idx * 16); }
#pragma unroll
    for (int r = 0; r < 16; r++) { int idx = r * 256 + tid; cpa16(sb + 131072 + idx * 16, srcB + (size_t)idx * 16); }
    CP_COMMIT(); CP_WAIT0();
    __syncthreads();

    int wm = w >> 1, wn = w & 1;
    const int aRow = ((lane >> 3) & 1) * 8 + (lane & 7);
    const int aKh  = lane >> 4;
    const int bRow = (lane >> 4) * 8 + (lane & 7);
    const int bKh  = (lane >> 3) & 1;

    float d[2][4][4] = {};
#pragma unroll
    for (int oc = 0; oc < 4; oc++) {
        u32 stA = sb + oc * 32768;
        u32 stB = sb + 131072 + oc * 16384;
#pragma unroll
        for (int k16 = 0; k16 < 4; k16++) {
            u32 aH[2][4], aL[2][4];
#pragma unroll
            for (int mi = 0; mi < 2; mi++) {
                u32 off = swz((u32)((wm * 32 + mi * 16 + aRow) * 128 + (k16 * 2 + aKh) * 16));
                ldsm4(aH[mi], stA + off);
                ldsm4(aL[mi], stA + 16384 + off);
            }
            u32 bH[2][4], bL[2][4];
#pragma unroll
            for (int bi = 0; bi < 2; bi++) {
                u32 off = swz((u32)((wn * 32 + bi * 16 + bRow) * 128 + (k16 * 2 + bKh) * 16));
                ldsm4(bH[bi], stB + off);
                ldsm4(bL[bi], stB + 8192 + off);
            }
#pragma unroll
            for (int mi = 0; mi < 2; mi++)
#pragma unroll
                for (int nj = 0; nj < 4; nj++) {
                    mma_bf16(d[mi][nj], aH[mi], &bH[nj >> 1][(nj & 1) * 2]);
                    mma_bf16(d[mi][nj], aH[mi], &bL[nj >> 1][(nj & 1) * 2]);
                    mma_bf16(d[mi][nj], aL[mi], &bH[nj >> 1][(nj & 1) * 2]);
                }
        }
    }

    char* th = (char*)&g_wbf[1][nT][kc][0];
#pragma unroll
    for (int mi = 0; mi < 2; mi++)
#pragma unroll
        for (int nj = 0; nj < 4; nj++)
#pragma unroll
            for (int rh = 0; rh < 2; rh++) {
                int n = wm * 32 + mi * 16 + (lane >> 2) + rh * 8;
                int j = rowj(nT, n);
                int k0l = wn * 32 + nj * 8 + 2 * (lane & 3);
                const float* wr = Whh + (size_t)j * 1024 + kc * 64 + k0l;
                u32 off = swz((u32)(n * 128 + k0l * 2));
                *(u32*)(th + off) = pack2h(d[mi][nj][rh * 2 + 0] + wr[0],
                                           d[mi][nj][rh * 2 + 1] + wr[1]);
            }
}

// ---------------- persistent LSTM: fp16 1-pass, 10 resident B chunks in smem ---------
// smem: [Bres 160KB][stage0: A16+B16][stage1: A16+B16] = 224KB. 128 CTAs resident.
#define BRES_BYTES 163840
#define LSTAGE 32768
#define LSTM_SMEM (BRES_BYTES + 2*LSTAGE + 1024)
__global__ __launch_bounds__(256, 1) void lstm_persist()
{
    extern __shared__ char smem[];
    u32 sb = (smem_u32(smem) + 1023) & ~1023u;
    const u32 sbStage = sb + BRES_BYTES;
    const int tid = threadIdx.x, lane = tid & 31, w = tid >> 5;
    const int mT = blockIdx.x, nT = blockIdx.y;
    const int wm = w >> 2, wn = w & 3;
    const int aRow = ((lane >> 3) & 1) * 8 + (lane & 7);
    const int aKh  = lane >> 4;
    const int bRow = (lane >> 4) * 8 + (lane & 7);
    const int bKh  = (lane >> 3) & 1;

    // preload resident B: chunks 0..9 of steady-state weights (16KB each)
    {
        const char* wres = (const char*)&g_wbf[1][nT][0][0];
#pragma unroll
        for (int r = 0; r < 40; r++) {
            int idx = r * 256 + tid;
            cpa16(sb + idx * 16, wres + (size_t)idx * 16);
        }
        CP_COMMIT(); CP_WAIT0();
        __syncthreads();
    }

    auto fillA = [&](int c, int s, const char* src) {
#pragma unroll
        for (int r = 0; r < 4; r++) {
            int idx = r * 256 + tid;
            cpa16(sbStage + s * LSTAGE + idx * 16, src + (size_t)c * 16384 + idx * 16);
        }
    };
    auto fillB = [&](int c, int s, const char* src) {
#pragma unroll
        for (int r = 0; r < 4; r++) {
            int idx = r * 256 + tid;
            cpa16(sbStage + s * LSTAGE + 16384 + idx * 16, src + (size_t)c * 16384 + idx * 16);
        }
    };

    float bZ[2][4], bF[2][4];
#pragma unroll
    for (int cp = 0; cp < 2; cp++) {
        int cell = nT * 32 + wn * 8 + cp * 4 + (lane & 3);
#pragma unroll
        for (int g = 0; g < 4; g++) {
            bZ[cp][g] = g_b0[g * 1024 + cell];
            bF[cp][g] = g_bf[g * 1024 + cell];
        }
    }

    float creg[4][2][2];
#pragma unroll
    for (int mi = 0; mi < 4; mi++)
#pragma unroll
        for (int rh = 0; rh < 2; rh++)
#pragma unroll
            for (int cp = 0; cp < 2; cp++) creg[mi][rh][cp] = 0.f;

    // prologue for t=1: B0,B1 (Whh), A0,A1 — 4 groups (order matters for wait_group 1)
    {
        const char* B1 = (const char*)&g_wbf[0][nT][0][0];
        const char* A1 = (const char*)&g_hbf[0][mT][0][0];
        fillB(0, 0, B1); CP_COMMIT();
        fillB(1, 1, B1); CP_COMMIT();
        fillA(0, 0, A1); CP_COMMIT();
        fillA(1, 1, A1); CP_COMMIT();
    }

    for (int t = 1; t <= 128; t++) {
        const int first = (t == 1);
        const char* srcA = (const char*)&g_hbf[t - 1][mT][0][0];
        const char* srcB = first ? (const char*)&g_wbf[0][nT][0][0]
                                 : (const char*)&g_wbf[1][nT][0][0];

        float d[4][4][4];
#pragma unroll
        for (int mi = 0; mi < 4; mi++)
#pragma unroll
            for (int nj = 0; nj < 4; nj++)
#pragma unroll
                for (int q = 0; q < 4; q++) d[mi][nj][q] = 0.f;

        for (int c = 0; c < 16; c++) {
            int s = c & 1;
            CP_WAIT1();
            __syncthreads();
            u32 stA = sbStage + s * LSTAGE;
            u32 stB = (!first && c < 10) ? (sb + c * 16384) : (stA + 16384);
#pragma unroll
            for (int k16 = 0; k16 < 4; k16++) {
                u32 aH[4][4];
#pragma unroll
                for (int mi = 0; mi < 4; mi++) {
                    u32 off = swz((u32)((wm * 64 + mi * 16 + aRow) * 128 + (k16 * 2 + aKh) * 16));
                    ldsm4(aH[mi], stA + off);
                }
                u32 bIFh[4], bGOh[4];
                {
                    u32 offIF = swz((u32)((wn * 16 + bRow) * 128 + (k16 * 2 + bKh) * 16));
                    u32 offGO = swz((u32)((64 + wn * 16 + bRow) * 128 + (k16 * 2 + bKh) * 16));
                    ldsm4(bIFh, stB + offIF);
                    ldsm4(bGOh, stB + offGO);
                }
#pragma unroll
                for (int mi = 0; mi < 4; mi++)
#pragma unroll
                    for (int nj = 0; nj < 2; nj++) {
                        mma_f16(d[mi][nj],     aH[mi], &bIFh[nj * 2]);
                        mma_f16(d[mi][nj + 2], aH[mi], &bGOh[nj * 2]);
                    }
            }
            __syncthreads();
            if (c + 2 < 16) {
                fillA(c + 2, s, srcA);
                if (first || c + 2 >= 10) fillB(c + 2, s, srcB);
            }
            CP_COMMIT();
        }

        // ---- epilogue: LSTM cell update (c in regs) + emit next A tile (hi-only) ----
        {
            const int chunk = nT >> 1;
            char* dh = (char*)&g_hbf[t][mT][chunk][0];
#pragma unroll
            for (int mi = 0; mi < 4; mi++)
#pragma unroll
                for (int rh = 0; rh < 2; rh++) {
                    int bl = wm * 64 + mi * 16 + (lane >> 2) + rh * 8;
#pragma unroll
                    for (int cp = 0; cp < 2; cp++) {
                        int cl = wn * 8 + cp * 4 + (lane & 3);
                        float gi = d[mi][cp][rh * 2 + 0]     + (first ? bZ[cp][0] : bF[cp][0]);
                        float gf = d[mi][cp][rh * 2 + 1]     + (first ? bZ[cp][1] : bF[cp][1]);
                        float gg = d[mi][cp + 2][rh * 2 + 0] + (first ? bZ[cp][2] : bF[cp][2]);
                        float go = d[mi][cp + 2][rh * 2 + 1] + (first ? bZ[cp][3] : bF[cp][3]);
                        float cold = first ? 0.f : creg[mi][rh][cp];
                        float cn = sigm(gf) * cold + sigm(gi) * tanhf(gg);
                        float hn = sigm(go) * tanhf(cn);
                        creg[mi][rh][cp] = cn;
                        int kin = (nT & 1) * 32 + cl;
                        u32 off = swz((u32)(bl * 128 + kin * 2));
                        *(__half*)(dh + off) = __float2half_rn(hn);
                    }
                }
        }

        if (t < 128) {
            __syncthreads();                 // all epilogue STGs issued
            if (tid == 0) {
                asm volatile("fence.release.gpu;" ::: "memory");
                u32* bp = &g_bar[t * 4 + mT];
                asm volatile("red.relaxed.gpu.global.add.u32 [%0], %1;" :: "l"(bp), "r"(1u) : "memory");
                u32 v;
                asm volatile("ld.relaxed.gpu.global.u32 %0, [%1];" : "=r"(v) : "l"(bp) : "memory");
                while (v < 32) {
                    asm volatile("nanosleep.u32 32;");
                    asm volatile("ld.relaxed.gpu.global.u32 %0, [%1];" : "=r"(v) : "l"(bp) : "memory");
                }
                asm volatile("fence.acquire.gpu;" ::: "memory");
            }
            __syncthreads();
            const char* An = (const char*)&g_hbf[t][mT][0][0];
            fillA(0, 0, An); CP_COMMIT();
            fillA(1, 1, An); CP_COMMIT();
        }
    }
}

// ---------------- output GEMM: fp16 2-pass (A hi, B split) ----------------
#define OSTAGE 49152
#define OUT_SMEM (2*OSTAGE + 1024)
__global__ __launch_bounds__(256, 1) void out_mma(const float* __restrict__ bout,
                                                  float* __restrict__ out)
{
    extern __shared__ char smem[];
    u32 sb = (smem_u32(smem) + 1023) & ~1023u;
    int tid = threadIdx.x, lane = tid & 31, w = tid >> 5;
    int mT = blockIdx.x, nOT = blockIdx.y, t = blockIdx.z;

    const char* srcA = (const char*)&g_hbf[t + 1][mT][0][0];   // 16KB/chunk
    const char* srcB = (const char*)&g_obf[nOT][0][0][0];      // 32KB/chunk (split)

    auto fillA = [&](int c, int s) {
#pragma unroll
        for (int r = 0; r < 4; r++) {
            int idx = r * 256 + tid;
            cpa16(sb + s * OSTAGE + idx * 16, srcA + (size_t)c * 16384 + idx * 16);
        }
    };
    auto fillB = [&](int c, int s) {
#pragma unroll
        for (int r = 0; r < 8; r++) {
            int idx = r * 256 + tid;
            cpa16(sb + s * OSTAGE + 16384 + idx * 16, srcB + (size_t)c * 32768 + idx * 16);
        }
    };

#pragma unroll
    for (int pc = 0; pc < 2; pc++) {
        fillA(pc, pc);
        fillB(pc, pc);
        CP_COMMIT();
    }

    int wm = w >> 2, wn = w & 3;
    const int aRow = ((lane >> 3) & 1) * 8 + (lane & 7);
    const int aKh  = lane >> 4;
    const int bRow = (lane >> 4) * 8 + (lane & 7);
    const int bKh  = (lane >> 3) & 1;

    float d[4][4][4] = {};

    for (int c = 0; c < 16; c++) {
        int s = c & 1;
        CP_WAIT1();
        __syncthreads();
        u32 stA = sb + s * OSTAGE;
        u32 stB = stA + 16384;
#pragma unroll
        for (int k16 = 0; k16 < 4; k16++) {
            u32 aH[4][4];
#pragma unroll
            for (int mi = 0; mi < 4; mi++) {
                u32 off = swz((u32)((wm * 64 + mi * 16 + aRow) * 128 + (k16 * 2 + aKh) * 16));
                ldsm4(aH[mi], stA + off);
            }
            u32 bH[2][4], bL[2][4];
#pragma unroll
            for (int bi = 0; bi < 2; bi++) {
                u32 off = swz((u32)((wn * 32 + bi * 16 + bRow) * 128 + (k16 * 2 + bKh) * 16));
                ldsm4(bH[bi], stB + off);
                ldsm4(bL[bi], stB + 16384 + off);
            }
#pragma unroll
            for (int mi = 0; mi < 4; mi++)
#pragma unroll
                for (int nj = 0; nj < 4; nj++) {
                    mma_f16(d[mi][nj], aH[mi], &bH[nj >> 1][(nj & 1) * 2]);
                    mma_f16(d[mi][nj], aH[mi], &bL[nj >> 1][(nj & 1) * 2]);
                }
        }
        __syncthreads();
        if (c + 2 < 16) {
            fillA(c + 2, s);
            fillB(c + 2, s);
        }
        CP_COMMIT();
    }

#pragma unroll
    for (int mi = 0; mi < 4; mi++)
#pragma unroll
        for (int nj = 0; nj < 4; nj++)
#pragma unroll
            for (int rh = 0; rh < 2; rh++) {
                int bl = wm * 64 + mi * 16 + (lane >> 2) + rh * 8;
                int b = mT * 128 + bl;
                int o = nOT * 128 + wn * 32 + nj * 8 + 2 * (lane & 3);
                float2 v = make_float2(d[mi][nj][rh * 2 + 0] + bout[o],
                                       d[mi][nj][rh * 2 + 1] + bout[o + 1]);
                *(float2*)&out[(size_t)b * 32768 + (size_t)t * 256 + o] = v;
            }
}

// ---------------- launch ----------------
extern "C" void kernel_launch(void* const* d_in, const int* in_sizes, int n_in,
                              void* d_out, int out_size)
{
    const float *enc = nullptr, *Wih = nullptr, *Whh = nullptr;
    const float *bih = nullptr, *bhh = nullptr, *Wout = nullptr, *bout = nullptr;
    for (int i = 0; i < n_in; i++) {
        int s = in_sizes[i];
        if      (s == 512 * 1024)  enc  = (const float*)d_in[i];
        else if (s == 4096 * 256)  Wih  = (const float*)d_in[i];
        else if (s == 4096 * 1024) Whh  = (const float*)d_in[i];
        else if (s == 4096)        { if (!bih) bih = (const float*)d_in[i]; else bhh = (const float*)d_in[i]; }
        else if (s == 256 * 1024)  Wout = (const float*)d_in[i];
        else if (s == 256)         bout = (const float*)d_in[i];
    }
    if (!enc || !Wih || !Whh || !bih || !bhh || !Wout || !bout) return;

    cudaFuncSetAttribute(prep_mma,     cudaFuncAttributeMaxDynamicSharedMemorySize, PREP_SMEM);
    cudaFuncSetAttribute(lstm_persist, cudaFuncAttributeMaxDynamicSharedMemorySize, LSTM_SMEM);
    cudaFuncSetAttribute(out_mma,      cudaFuncAttributeMaxDynamicSharedMemorySize, OUT_SMEM);

    init_bar<<<3, 256>>>();
    prep_bias<<<512, 256>>>(Wih, bih, bhh, bout);
    conv_w0<<<dim3(16, 32), 256>>>(Whh);
    conv_wih<<<dim3(4, 32), 256>>>(Wih);
    conv_woutT<<<dim3(4, 16), 256>>>(Wout);
    conv_obf<<<dim3(16, 2), 256>>>(Wout);
    conv_h0<<<dim3(16, 4), 256>>>(enc);
    prep_mma<<<dim3(32, 16), 256, PREP_SMEM>>>(Whh);

    lstm_persist<<<dim3(4, 32), 256, LSTM_SMEM>>>();

    out_mma<<<dim3(4, 2, 128), 256, OUT_SMEM>>>(bout, (float*)d_out);
    (void)out_size;
}

// round 11
// speedup vs baseline: 2.2003x; 1.0133x over previous
#include <cuda_runtime.h>
#include <cuda_bf16.h>
#include <cuda_fp16.h>
#include <cstdint>

typedef unsigned long long ull;
typedef unsigned int u32;

// ---------------- scratch (static __device__, no allocations) ----------------
static __device__ float g_b0[4096];               // b_ih+b_hh
static __device__ float g_bf[4096];               // + W_ih@b_out
static __device__ u32   g_bar[516];               // per-(t,mT) arrival counters
// fp16 HI-ONLY weight tiles, gate-paired rows, SW128: [src][nT 32][chunk 16][128x64]
static __device__ __align__(256) __half g_wbf[2][32][16][8192];
// fp16 HI-ONLY hidden tiles: [t 0..128][mT 4][chunk 16][128x64]
static __device__ __align__(256) __half g_hbf[129][4][16][8192];
// fp16 SPLIT output-weight tiles: [nOT 2][chunk 16][part 2][128x64] (only hi used now)
static __device__ __align__(256) __half g_obf[2][16][2][8192];
// prep-GEMM operands (bf16 split, 3-pass prep path)
static __device__ __align__(256) __nv_bfloat16 g_pA[32][4][2][8192];
static __device__ __align__(256) __nv_bfloat16 g_pB[16][4][2][4096];

// ---------------- helpers ----------------
__device__ __forceinline__ float sigm(float x) { return 1.0f / (1.0f + __expf(-x)); }
__device__ __forceinline__ u32 swz(u32 x) { return x ^ ((x >> 3) & 0x70); }
__device__ __forceinline__ u32 smem_u32(const void* p) {
    u32 a; asm("{ .reg .u64 t; cvta.to.shared.u64 t, %1; cvt.u32.u64 %0, t; }" : "=r"(a) : "l"(p));
    return a;
}
__device__ __forceinline__ void cpa16(u32 dst, const void* src) {
    asm volatile("cp.async.cg.shared.global [%0], [%1], 16;" :: "r"(dst), "l"(src));
}
#define CP_COMMIT() asm volatile("cp.async.commit_group;" ::: "memory")
#define CP_WAIT0()  asm volatile("cp.async.wait_group 0;" ::: "memory")

// ---- bulk copy + mbarrier (sm_90+ base ISA; verified to compile on sm_103 in R2) ----
__device__ __forceinline__ void bulk_g2s(u32 dst, const void* src, u32 bytes, u32 mbar) {
    asm volatile("cp.async.bulk.shared::cta.global.mbarrier::complete_tx::bytes [%0], [%1], %2, [%3];"
                 :: "r"(dst), "l"(src), "r"(bytes), "r"(mbar) : "memory");
}
__device__ __forceinline__ void mbar_init(u32 a, u32 cnt) {
    asm volatile("mbarrier.init.shared.b64 [%0], %1;" :: "r"(a), "r"(cnt) : "memory");
}
__device__ __forceinline__ void mbar_expect(u32 a, u32 tx) {
    asm volatile("mbarrier.arrive.expect_tx.shared.b64 _, [%0], %1;" :: "r"(a), "r"(tx) : "memory");
}
__device__ __forceinline__ void mbar_wait(u32 a, u32 ph) {
    asm volatile("{\n\t.reg .pred P;\n\t"
                 "WL_%=:\n\t"
                 "mbarrier.try_wait.parity.acquire.cta.shared::cta.b64 P, [%0], %1, 0x989680;\n\t"
                 "@P bra.uni WD_%=;\n\t"
                 "bra.uni WL_%=;\n\t"
                 "WD_%=:\n\t}"
                 :: "r"(a), "r"(ph) : "memory");
}

__device__ __forceinline__ void ldsm4(u32* r, u32 addr) {
    asm volatile("ldmatrix.sync.aligned.m8n8.x4.shared.b16 {%0,%1,%2,%3}, [%4];"
                 : "=r"(r[0]), "=r"(r[1]), "=r"(r[2]), "=r"(r[3]) : "r"(addr));
}
__device__ __forceinline__ void mma_bf16(float* d, const u32* a, const u32* b) {
    asm volatile("mma.sync.aligned.m16n8k16.row.col.f32.bf16.bf16.f32 "
                 "{%0,%1,%2,%3}, {%4,%5,%6,%7}, {%8,%9}, {%0,%1,%2,%3};"
                 : "+f"(d[0]), "+f"(d[1]), "+f"(d[2]), "+f"(d[3])
                 : "r"(a[0]), "r"(a[1]), "r"(a[2]), "r"(a[3]), "r"(b[0]), "r"(b[1]));
}
__device__ __forceinline__ void mma_f16(float* d, const u32* a, const u32* b) {
    asm volatile("mma.sync.aligned.m16n8k16.row.col.f32.f16.f16.f32 "
                 "{%0,%1,%2,%3}, {%4,%5,%6,%7}, {%8,%9}, {%0,%1,%2,%3};"
                 : "+f"(d[0]), "+f"(d[1]), "+f"(d[2]), "+f"(d[3])
                 : "r"(a[0]), "r"(a[1]), "r"(a[2]), "r"(a[3]), "r"(b[0]), "r"(b[1]));
}
__device__ __forceinline__ void split_h16(float v, __half& h, __half& l) {
    h = __float2half_rn(v);
    l = __float2half_rn(v - __half2float(h));
}
__device__ __forceinline__ u32 pack2h(float v0, float v1) {
    __half h0 = __float2half_rn(v0), h1 = __float2half_rn(v1);
    return (u32)__half_as_ushort(h0) | ((u32)__half_as_ushort(h1) << 16);
}
__device__ __forceinline__ u32 pack_split2h(float v0, float v1, u32& lo_out) {
    __half h0, l0, h1, l1;
    split_h16(v0, h0, l0); split_h16(v1, h1, l1);
    lo_out = (u32)__half_as_ushort(l0) | ((u32)__half_as_ushort(l1) << 16);
    return (u32)__half_as_ushort(h0) | ((u32)__half_as_ushort(h1) << 16);
}
__device__ __forceinline__ void split_bf(float v, __nv_bfloat16& h, __nv_bfloat16& l) {
    h = __float2bfloat16(v);
    l = __float2bfloat16(v - __bfloat162float(h));
}
// gate-paired row -> j (j = gate*1024 + cell)
__device__ __forceinline__ int rowj(int nT, int n) {
    int half = n >> 6, m = n & 63;
    return (half * 2 + (m & 1)) * 1024 + nT * 32 + (m >> 1);
}

// ---------------- init barrier counters ----------------
__global__ void init_bar() {
    int i = blockIdx.x * 256 + threadIdx.x;
    if (i < 516) g_bar[i] = 0;
}

// ---------------- prep: biases (warp per j) ----------------
__global__ void prep_bias(const float* __restrict__ Wih, const float* __restrict__ bih,
                          const float* __restrict__ bhh, const float* __restrict__ bout)
{
    int w = threadIdx.x >> 5, lane = threadIdx.x & 31;
    int j = blockIdx.x * 8 + w;
    float acc = 0.f;
#pragma unroll
    for (int i = 0; i < 8; i++) acc += Wih[(size_t)j * 256 + i * 32 + lane] * bout[i * 32 + lane];
#pragma unroll
    for (int o = 16; o; o >>= 1) acc += __shfl_xor_sync(0xFFFFFFFFu, acc, o);
    if (lane == 0) {
        float s = bih[j] + bhh[j];
        g_b0[j] = s;
        g_bf[j] = s + acc;
    }
}

// ---------------- conv: Whh -> g_wbf[0] (fp16 hi-only, coalesced) ----------------
__global__ void conv_w0(const float* __restrict__ Whh)
{
    int chunk = blockIdx.x, nT = blockIdx.y;
    int w = threadIdx.x >> 5, lane = threadIdx.x & 31;
    char* th = (char*)&g_wbf[0][nT][chunk][0];
#pragma unroll
    for (int r = 0; r < 16; r++) {
        int n = r * 8 + w;
        const float2 v2 = *(const float2*)&Whh[(size_t)rowj(nT, n) * 1024 + chunk * 64 + lane * 2];
        u32 off = swz((u32)(n * 128 + lane * 4));
        *(u32*)(th + off) = pack2h(v2.x, v2.y);
    }
}

// ---------------- conv: Wih -> g_pA (bf16 split, prep path) ----------------
__global__ void conv_wih(const float* __restrict__ Wih)
{
    int oc = blockIdx.x, nT = blockIdx.y;
    int w = threadIdx.x >> 5, lane = threadIdx.x & 31;
    char* th = (char*)&g_pA[nT][oc][0][0];
    char* tl = th + 16384;
#pragma unroll
    for (int r = 0; r < 16; r++) {
        int n = r * 8 + w;
        const float2 v2 = *(const float2*)&Wih[(size_t)rowj(nT, n) * 256 + oc * 64 + lane * 2];
        __nv_bfloat16 h0, l0, h1, l1;
        split_bf(v2.x, h0, l0); split_bf(v2.y, h1, l1);
        u32 hi = (u32)__bfloat16_as_ushort(h0) | ((u32)__bfloat16_as_ushort(h1) << 16);
        u32 lo = (u32)__bfloat16_as_ushort(l0) | ((u32)__bfloat16_as_ushort(l1) << 16);
        u32 off = swz((u32)(n * 128 + lane * 4));
        *(u32*)(th + off) = hi;
        *(u32*)(tl + off) = lo;
    }
}

// ---------------- conv: Wout^T -> g_pB (bf16 split, prep path) ----------------
__global__ void conv_woutT(const float* __restrict__ Wout)
{
    int oc = blockIdx.x, kc = blockIdx.y;
    int k = threadIdx.x & 63, og = threadIdx.x >> 6;
    char* th = (char*)&g_pB[kc][oc][0][0];
    char* tl = th + 8192;
#pragma unroll
    for (int i = 0; i < 16; i++) {
        int oo = og * 16 + i;
        float v = Wout[(size_t)(oc * 64 + oo) * 1024 + kc * 64 + k];
        __nv_bfloat16 h, l; split_bf(v, h, l);
        u32 off = swz((u32)(k * 128 + oo * 2));
        *(__nv_bfloat16*)(th + off) = h;
        *(__nv_bfloat16*)(tl + off) = l;
    }
}

// ---------------- conv: Wout -> g_obf (fp16 split; hi used by out_mma) ----------------
__global__ void conv_obf(const float* __restrict__ Wout)
{
    int chunk = blockIdx.x, nOT = blockIdx.y;
    int w = threadIdx.x >> 5, lane = threadIdx.x & 31;
    char* th = (char*)&g_obf[nOT][chunk][0][0];
    char* tl = th + 16384;
#pragma unroll
    for (int r = 0; r < 16; r++) {
        int n = r * 8 + w;
        const float2 v2 = *(const float2*)&Wout[(size_t)(nOT * 128 + n) * 1024 + chunk * 64 + lane * 2];
        u32 lo, hi = pack_split2h(v2.x, v2.y, lo);
        u32 off = swz((u32)(n * 128 + lane * 4));
        *(u32*)(th + off) = hi;
        *(u32*)(tl + off) = lo;
    }
}

// ---------------- conv: encoder h0 -> g_hbf[0] (fp16 hi-only) ----------------
__global__ void conv_h0(const float* __restrict__ enc)
{
    int chunk = blockIdx.x, mT = blockIdx.y;
    int w = threadIdx.x >> 5, lane = threadIdx.x & 31;
    char* th = (char*)&g_hbf[0][mT][chunk][0];
#pragma unroll
    for (int r = 0; r < 16; r++) {
        int m = r * 8 + w;
        const float2 v2 = *(const float2*)&enc[(size_t)(mT * 128 + m) * 1024 + chunk * 64 + lane * 2];
        u32 off = swz((u32)(m * 128 + lane * 4));
        *(u32*)(th + off) = pack2h(v2.x, v2.y);
    }
}

// ---------------- prep GEMM: g_wbf[1] = fp16(Whh + Wih @ Wout^T), bf16 3-pass -------
#define PREP_SMEM (128*1024 + 64*1024 + 1024)
__global__ __launch_bounds__(256, 1) void prep_mma(const float* __restrict__ Whh)
{
    extern __shared__ char smem[];
    u32 sb = (smem_u32(smem) + 1023) & ~1023u;
    int tid = threadIdx.x, lane = tid & 31, w = tid >> 5;
    int nT = blockIdx.x, kc = blockIdx.y;

    const char* srcA = (const char*)&g_pA[nT][0][0][0];
    const char* srcB = (const char*)&g_pB[kc][0][0][0];
#pragma unroll
    for (int r = 0; r < 32; r++) { int idx = r * 256 + tid; cpa16(sb + idx * 16, srcA + (size_t)idx * 16); }
#pragma unroll
    for (int r = 0; r < 16; r++) { int idx = r * 256 + tid; cpa16(sb + 131072 + idx * 16, srcB + (size_t)idx * 16); }
    CP_COMMIT(); CP_WAIT0();
    __syncthreads();

    int wm = w >> 1, wn = w & 1;
    const int aRow = ((lane >> 3) & 1) * 8 + (lane & 7);
    const int aKh  = lane >> 4;
    const int bRow = (lane >> 4) * 8 + (lane & 7);
    const int bKh  = (lane >> 3) & 1;

    float d[2][4][4] = {};
#pragma unroll
    for (int oc = 0; oc < 4; oc++) {
        u32 stA = sb + oc * 32768;
        u32 stB = sb + 131072 + oc * 16384;
#pragma unroll
        for (int k16 = 0; k16 < 4; k16++) {
            u32 aH[2][4], aL[2][4];
#pragma unroll
            for (int mi = 0; mi < 2; mi++) {
                u32 off = swz((u32)((wm * 32 + mi * 16 + aRow) * 128 + (k16 * 2 + aKh) * 16));
                ldsm4(aH[mi], stA + off);
                ldsm4(aL[mi], stA + 16384 + off);
            }
            u32 bH[2][4], bL[2][4];
#pragma unroll
            for (int bi = 0; bi < 2; bi++) {
                u32 off = swz((u32)((wn * 32 + bi * 16 + bRow) * 128 + (k16 * 2 + bKh) * 16));
                ldsm4(bH[bi], stB + off);
                ldsm4(bL[bi], stB + 8192 + off);
            }
#pragma unroll
            for (int mi = 0; mi < 2; mi++)
#pragma unroll
                for (int nj = 0; nj < 4; nj++) {
                    mma_bf16(d[mi][nj], aH[mi], &bH[nj >> 1][(nj & 1) * 2]);
                    mma_bf16(d[mi][nj], aH[mi], &bL[nj >> 1][(nj & 1) * 2]);
                    mma_bf16(d[mi][nj], aL[mi], &bH[nj >> 1][(nj & 1) * 2]);
                }
        }
    }

    char* th = (char*)&g_wbf[1][nT][kc][0];
#pragma unroll
    for (int mi = 0; mi < 2; mi++)
#pragma unroll
        for (int nj = 0; nj < 4; nj++)
#pragma unroll
            for (int rh = 0; rh < 2; rh++) {
                int n = wm * 32 + mi * 16 + (lane >> 2) + rh * 8;
                int j = rowj(nT, n);
                int k0l = wn * 32 + nj * 8 + 2 * (lane & 3);
                const float* wr = Whh + (size_t)j * 1024 + kc * 64 + k0l;
                u32 off = swz((u32)(n * 128 + k0l * 2));
                *(u32*)(th + off) = pack2h(d[mi][nj][rh * 2 + 0] + wr[0],
                                           d[mi][nj][rh * 2 + 1] + wr[1]);
            }
}

// ---------------- persistent LSTM: fp16 1-pass, bulk-copy pipeline ----------------
// smem: [1024 mbar][Bres 160KB][stage0: A16+B16][stage1: A16+B16]
#define BRES_BYTES 163840
#define LSTAGE 32768
#define LSTM_SMEM (1024 + 1024 + BRES_BYTES + 2*LSTAGE)
__global__ __launch_bounds__(256, 1) void lstm_persist()
{
    extern __shared__ char smem[];
    u32 sb = (smem_u32(smem) + 1023) & ~1023u;
    const u32 mb0 = sb, mb1 = sb + 16, mbP = sb + 32;
    const u32 sbBres  = sb + 1024;
    const u32 sbStage = sbBres + BRES_BYTES;
    const int tid = threadIdx.x, lane = tid & 31, w = tid >> 5;
    const int mT = blockIdx.x, nT = blockIdx.y;
    const int wm = w >> 2, wn = w & 3;
    const int aRow = ((lane >> 3) & 1) * 8 + (lane & 7);
    const int aKh  = lane >> 4;
    const int bRow = (lane >> 4) * 8 + (lane & 7);
    const int bKh  = (lane >> 3) & 1;

    if (tid == 0) {
        mbar_init(mb0, 1);
        mbar_init(mb1, 1);
        mbar_init(mbP, 1);
        asm volatile("fence.proxy.async.shared::cta;" ::: "memory");
    }
    __syncthreads();

    // preload resident B (chunks 0..9 of steady-state weights) + t=1 prologue
    if (tid == 0) {
        const char* wres = (const char*)&g_wbf[1][nT][0];
        mbar_expect(mbP, BRES_BYTES);
#pragma unroll
        for (int c = 0; c < 10; c++)
            bulk_g2s(sbBres + c * 16384, wres + (size_t)c * 16384, 16384, mbP);

        const char* B1 = (const char*)&g_wbf[0][nT][0];
        const char* A1 = (const char*)&g_hbf[0][mT][0];
        mbar_expect(mb0, 32768);
        bulk_g2s(sbStage, A1, 16384, mb0);
        bulk_g2s(sbStage + 16384, B1, 16384, mb0);
        mbar_expect(mb1, 32768);
        bulk_g2s(sbStage + LSTAGE, A1 + 16384, 16384, mb1);
        bulk_g2s(sbStage + LSTAGE + 16384, B1 + 16384, 16384, mb1);
    }
    mbar_wait(mbP, 0);

    float bZ[2][4], bF[2][4];
#pragma unroll
    for (int cp = 0; cp < 2; cp++) {
        int cell = nT * 32 + wn * 8 + cp * 4 + (lane & 3);
#pragma unroll
        for (int g = 0; g < 4; g++) {
            bZ[cp][g] = g_b0[g * 1024 + cell];
            bF[cp][g] = g_bf[g * 1024 + cell];
        }
    }

    float creg[4][2][2];
#pragma unroll
    for (int mi = 0; mi < 4; mi++)
#pragma unroll
        for (int rh = 0; rh < 2; rh++)
#pragma unroll
            for (int cp = 0; cp < 2; cp++) creg[mi][rh][cp] = 0.f;

    u32 ph0 = 0, ph1 = 0;

    for (int t = 1; t <= 128; t++) {
        const int first = (t == 1);
        const char* srcA = (const char*)&g_hbf[t - 1][mT][0];
        const char* srcB = first ? (const char*)&g_wbf[0][nT][0]
                                 : (const char*)&g_wbf[1][nT][0];

        float d[4][4][4];
#pragma unroll
        for (int mi = 0; mi < 4; mi++)
#pragma unroll
            for (int nj = 0; nj < 4; nj++)
#pragma unroll
                for (int q = 0; q < 4; q++) d[mi][nj][q] = 0.f;

        for (int c = 0; c < 16; c++) {
            int s = c & 1;
            u32 mbs = s ? mb1 : mb0;
            if (s) { mbar_wait(mb1, ph1); ph1 ^= 1; }
            else   { mbar_wait(mb0, ph0); ph0 ^= 1; }
            u32 stA = sbStage + s * LSTAGE;
            u32 stB = (!first && c < 10) ? (sbBres + c * 16384) : (stA + 16384);
#pragma unroll
            for (int k16 = 0; k16 < 4; k16++) {
                u32 aH[4][4];
#pragma unroll
                for (int mi = 0; mi < 4; mi++) {
                    u32 off = swz((u32)((wm * 64 + mi * 16 + aRow) * 128 + (k16 * 2 + aKh) * 16));
                    ldsm4(aH[mi], stA + off);
                }
                u32 bIFh[4], bGOh[4];
                {
                    u32 offIF = swz((u32)((wn * 16 + bRow) * 128 + (k16 * 2 + bKh) * 16));
                    u32 offGO = swz((u32)((64 + wn * 16 + bRow) * 128 + (k16 * 2 + bKh) * 16));
                    ldsm4(bIFh, stB + offIF);
                    ldsm4(bGOh, stB + offGO);
                }
#pragma unroll
                for (int mi = 0; mi < 4; mi++)
#pragma unroll
                    for (int nj = 0; nj < 2; nj++) {
                        mma_f16(d[mi][nj],     aH[mi], &bIFh[nj * 2]);
                        mma_f16(d[mi][nj + 2], aH[mi], &bGOh[nj * 2]);
                    }
            }
            __syncthreads();   // all warps done reading stage s -> safe to refill
            if (tid == 0 && c + 2 < 16) {
                int cn = c + 2;
                int bStream = (first || cn >= 10);
                mbar_expect(mbs, bStream ? 32768u : 16384u);
                bulk_g2s(stA, srcA + (size_t)cn * 16384, 16384, mbs);
                if (bStream)
                    bulk_g2s(stA + 16384, srcB + (size_t)cn * 16384, 16384, mbs);
            }
        }

        // ---- epilogue: LSTM cell update (c in regs) + emit next A tile (hi-only) ----
        {
            const int chunk = nT >> 1;
            char* dh = (char*)&g_hbf[t][mT][chunk][0];
#pragma unroll
            for (int mi = 0; mi < 4; mi++)
#pragma unroll
                for (int rh = 0; rh < 2; rh++) {
                    int bl = wm * 64 + mi * 16 + (lane >> 2) + rh * 8;
#pragma unroll
                    for (int cp = 0; cp < 2; cp++) {
                        int cl = wn * 8 + cp * 4 + (lane & 3);
                        float gi = d[mi][cp][rh * 2 + 0]     + (first ? bZ[cp][0] : bF[cp][0]);
                        float gf = d[mi][cp][rh * 2 + 1]     + (first ? bZ[cp][1] : bF[cp][1]);
                        float gg = d[mi][cp + 2][rh * 2 + 0] + (first ? bZ[cp][2] : bF[cp][2]);
                        float go = d[mi][cp + 2][rh * 2 + 1] + (first ? bZ[cp][3] : bF[cp][3]);
                        float cold = first ? 0.f : creg[mi][rh][cp];
                        float cn = sigm(gf) * cold + sigm(gi) * tanhf(gg);
                        float hn = sigm(go) * tanhf(cn);
                        creg[mi][rh][cp] = cn;
                        int kin = (nT & 1) * 32 + cl;
                        u32 off = swz((u32)(bl * 128 + kin * 2));
                        *(__half*)(dh + off) = __float2half_rn(hn);
                    }
                }
        }

        if (t < 128) {
            __syncthreads();                 // all epilogue STGs issued
            if (tid == 0) {
                asm volatile("fence.release.gpu;" ::: "memory");
                u32* bp = &g_bar[t * 4 + mT];
                asm volatile("red.relaxed.gpu.global.add.u32 [%0], %1;" :: "l"(bp), "r"(1u) : "memory");
                u32 v;
                asm volatile("ld.relaxed.gpu.global.u32 %0, [%1];" : "=r"(v) : "l"(bp) : "memory");
                while (v < 32) {
                    asm volatile("nanosleep.u32 32;");
                    asm volatile("ld.relaxed.gpu.global.u32 %0, [%1];" : "=r"(v) : "l"(bp) : "memory");
                }
                asm volatile("fence.acquire.gpu;" ::: "memory");
                // reload A chunks 0/1 of the new step (B resident)
                const char* An = (const char*)&g_hbf[t][mT][0];
                mbar_expect(mb0, 16384);
                bulk_g2s(sbStage, An, 16384, mb0);
                mbar_expect(mb1, 16384);
                bulk_g2s(sbStage + LSTAGE, An + 16384, 16384, mb1);
            }
            __syncthreads();
        }
    }
}

// ---------------- output GEMM: fp16 1-pass, bulk pipeline ----------------
#define OSTAGE 32768
#define OUT_SMEM (1024 + 1024 + 2*OSTAGE)
__global__ __launch_bounds__(256, 1) void out_mma(const float* __restrict__ bout,
                                                  float* __restrict__ out)
{
    extern __shared__ char smem[];
    u32 sb = (smem_u32(smem) + 1023) & ~1023u;
    const u32 mb0 = sb, mb1 = sb + 16;
    const u32 sbStage = sb + 1024;
    int tid = threadIdx.x, lane = tid & 31, w = tid >> 5;
    int mT = blockIdx.x, nOT = blockIdx.y, t = blockIdx.z;

    const char* srcA = (const char*)&g_hbf[t + 1][mT][0];      // 16KB/chunk
    const char* srcB = (const char*)&g_obf[nOT][0][0][0];      // hi at +0, 32KB chunk stride

    if (tid == 0) {
        mbar_init(mb0, 1);
        mbar_init(mb1, 1);
        asm volatile("fence.proxy.async.shared::cta;" ::: "memory");
    }
    __syncthreads();

    if (tid == 0) {
        mbar_expect(mb0, 32768);
        bulk_g2s(sbStage, srcA, 16384, mb0);
        bulk_g2s(sbStage + 16384, srcB, 16384, mb0);
        mbar_expect(mb1, 32768);
        bulk_g2s(sbStage + OSTAGE, srcA + 16384, 16384, mb1);
        bulk_g2s(sbStage + OSTAGE + 16384, srcB + 32768, 16384, mb1);
    }

    int wm = w >> 2, wn = w & 3;
    const int aRow = ((lane >> 3) & 1) * 8 + (lane & 7);
    const int aKh  = lane >> 4;
    const int bRow = (lane >> 4) * 8 + (lane & 7);
    const int bKh  = (lane >> 3) & 1;

    float d[4][4][4] = {};
    u32 ph0 = 0, ph1 = 0;

    for (int c = 0; c < 16; c++) {
        int s = c & 1;
        u32 mbs = s ? mb1 : mb0;
        if (s) { mbar_wait(mb1, ph1); ph1 ^= 1; }
        else   { mbar_wait(mb0, ph0); ph0 ^= 1; }
        u32 stA = sbStage + s * OSTAGE;
        u32 stB = stA + 16384;
#pragma unroll
        for (int k16 = 0; k16 < 4; k16++) {
            u32 aH[4][4];
#pragma unroll
            for (int mi = 0; mi < 4; mi++) {
                u32 off = swz((u32)((wm * 64 + mi * 16 + aRow) * 128 + (k16 * 2 + aKh) * 16));
                ldsm4(aH[mi], stA + off);
            }
            u32 bH[2][4];
#pragma unroll
            for (int bi = 0; bi < 2; bi++) {
                u32 off = swz((u32)((wn * 32 + bi * 16 + bRow) * 128 + (k16 * 2 + bKh) * 16));
                ldsm4(bH[bi], stB + off);
            }
#pragma unroll
            for (int mi = 0; mi < 4; mi++)
#pragma unroll
                for (int nj = 0; nj < 4; nj++)
                    mma_f16(d[mi][nj], aH[mi], &bH[nj >> 1][(nj & 1) * 2]);
        }
        __syncthreads();
        if (tid == 0 && c + 2 < 16) {
            int cn = c + 2;
            mbar_expect(mbs, 32768);
            bulk_g2s(stA, srcA + (size_t)cn * 16384, 16384, mbs);
            bulk_g2s(stB, srcB + (size_t)cn * 32768, 16384, mbs);
        }
    }

#pragma unroll
    for (int mi = 0; mi < 4; mi++)
#pragma unroll
        for (int nj = 0; nj < 4; nj++)
#pragma unroll
            for (int rh = 0; rh < 2; rh++) {
                int bl = wm * 64 + mi * 16 + (lane >> 2) + rh * 8;
                int b = mT * 128 + bl;
                int o = nOT * 128 + wn * 32 + nj * 8 + 2 * (lane & 3);
                float2 v = make_float2(d[mi][nj][rh * 2 + 0] + bout[o],
                                       d[mi][nj][rh * 2 + 1] + bout[o + 1]);
                *(float2*)&out[(size_t)b * 32768 + (size_t)t * 256 + o] = v;
            }
}

// ---------------- launch ----------------
extern "C" void kernel_launch(void* const* d_in, const int* in_sizes, int n_in,
                              void* d_out, int out_size)
{
    const float *enc = nullptr, *Wih = nullptr, *Whh = nullptr;
    const float *bih = nullptr, *bhh = nullptr, *Wout = nullptr, *bout = nullptr;
    for (int i = 0; i < n_in; i++) {
        int s = in_sizes[i];
        if      (s == 512 * 1024)  enc  = (const float*)d_in[i];
        else if (s == 4096 * 256)  Wih  = (const float*)d_in[i];
        else if (s == 4096 * 1024) Whh  = (const float*)d_in[i];
        else if (s == 4096)        { if (!bih) bih = (const float*)d_in[i]; else bhh = (const float*)d_in[i]; }
        else if (s == 256 * 1024)  Wout = (const float*)d_in[i];
        else if (s == 256)         bout = (const float*)d_in[i];
    }
    if (!enc || !Wih || !Whh || !bih || !bhh || !Wout || !bout) return;

    cudaFuncSetAttribute(prep_mma,     cudaFuncAttributeMaxDynamicSharedMemorySize, PREP_SMEM);
    cudaFuncSetAttribute(lstm_persist, cudaFuncAttributeMaxDynamicSharedMemorySize, LSTM_SMEM);
    cudaFuncSetAttribute(out_mma,      cudaFuncAttributeMaxDynamicSharedMemorySize, OUT_SMEM);

    init_bar<<<3, 256>>>();
    prep_bias<<<512, 256>>>(Wih, bih, bhh, bout);
    conv_w0<<<dim3(16, 32), 256>>>(Whh);
    conv_wih<<<dim3(4, 32), 256>>>(Wih);
    conv_woutT<<<dim3(4, 16), 256>>>(Wout);
    conv_obf<<<dim3(16, 2), 256>>>(Wout);
    conv_h0<<<dim3(16, 4), 256>>>(enc);
    prep_mma<<<dim3(32, 16), 256, PREP_SMEM>>>(Whh);

    lstm_persist<<<dim3(4, 32), 256, LSTM_SMEM>>>();

    out_mma<<<dim3(4, 2, 128), 256, OUT_SMEM>>>(bout, (float*)d_out);
    (void)out_size;
}

// round 12
// speedup vs baseline: 2.3609x; 1.0730x over previous
#include <cuda_runtime.h>
#include <cuda_bf16.h>
#include <cuda_fp16.h>
#include <cstdint>

typedef unsigned long long ull;
typedef unsigned int u32;

// ---------------- scratch (static __device__, no allocations) ----------------
static __device__ float g_b0[4096];               // b_ih+b_hh
static __device__ float g_bf[4096];               // + W_ih@b_out
static __device__ u32   g_bar[516];               // per-(t,mT) arrival counters, t=1..128
// fp16 HI-ONLY weight tiles, gate-paired rows, SW128: [src][nT 32][chunk 16][128x64]
static __device__ __align__(256) __half g_wbf[2][32][16][8192];
// fp16 HI-ONLY hidden tiles: [t 0..128][mT 4][chunk 16][128x64]
static __device__ __align__(256) __half g_hbf[129][4][16][8192];
// fp16 output-weight tiles: [nOT 2][chunk 16][part 2][128x64] (hi at part 0)
static __device__ __align__(256) __half g_obf[2][16][2][8192];
// prep-GEMM operands (bf16 split, 3-pass prep path)
static __device__ __align__(256) __nv_bfloat16 g_pA[32][4][2][8192];
static __device__ __align__(256) __nv_bfloat16 g_pB[16][4][2][4096];

// ---------------- helpers ----------------
__device__ __forceinline__ float sigm(float x) { return 1.0f / (1.0f + __expf(-x)); }
__device__ __forceinline__ u32 swz(u32 x) { return x ^ ((x >> 3) & 0x70); }
__device__ __forceinline__ u32 smem_u32(const void* p) {
    u32 a; asm("{ .reg .u64 t; cvta.to.shared.u64 t, %1; cvt.u32.u64 %0, t; }" : "=r"(a) : "l"(p));
    return a;
}
__device__ __forceinline__ void cpa16(u32 dst, const void* src) {
    asm volatile("cp.async.cg.shared.global [%0], [%1], 16;" :: "r"(dst), "l"(src));
}
#define CP_COMMIT() asm volatile("cp.async.commit_group;" ::: "memory")
#define CP_WAIT0()  asm volatile("cp.async.wait_group 0;" ::: "memory")

// ---- bulk copy + mbarrier ----
__device__ __forceinline__ void bulk_g2s(u32 dst, const void* src, u32 bytes, u32 mbar) {
    asm volatile("cp.async.bulk.shared::cta.global.mbarrier::complete_tx::bytes [%0], [%1], %2, [%3];"
                 :: "r"(dst), "l"(src), "r"(bytes), "r"(mbar) : "memory");
}
__device__ __forceinline__ void mbar_init(u32 a, u32 cnt) {
    asm volatile("mbarrier.init.shared.b64 [%0], %1;" :: "r"(a), "r"(cnt) : "memory");
}
__device__ __forceinline__ void mbar_expect(u32 a, u32 tx) {
    asm volatile("mbarrier.arrive.expect_tx.shared.b64 _, [%0], %1;" :: "r"(a), "r"(tx) : "memory");
}
__device__ __forceinline__ void mbar_wait(u32 a, u32 ph) {
    asm volatile("{\n\t.reg .pred P;\n\t"
                 "WL_%=:\n\t"
                 "mbarrier.try_wait.parity.acquire.cta.shared::cta.b64 P, [%0], %1, 0x989680;\n\t"
                 "@P bra.uni WD_%=;\n\t"
                 "bra.uni WL_%=;\n\t"
                 "WD_%=:\n\t}"
                 :: "r"(a), "r"(ph) : "memory");
}

__device__ __forceinline__ void ldsm4(u32* r, u32 addr) {
    asm volatile("ldmatrix.sync.aligned.m8n8.x4.shared.b16 {%0,%1,%2,%3}, [%4];"
                 : "=r"(r[0]), "=r"(r[1]), "=r"(r[2]), "=r"(r[3]) : "r"(addr));
}
__device__ __forceinline__ void mma_bf16(float* d, const u32* a, const u32* b) {
    asm volatile("mma.sync.aligned.m16n8k16.row.col.f32.bf16.bf16.f32 "
                 "{%0,%1,%2,%3}, {%4,%5,%6,%7}, {%8,%9}, {%0,%1,%2,%3};"
                 : "+f"(d[0]), "+f"(d[1]), "+f"(d[2]), "+f"(d[3])
                 : "r"(a[0]), "r"(a[1]), "r"(a[2]), "r"(a[3]), "r"(b[0]), "r"(b[1]));
}
__device__ __forceinline__ void mma_f16(float* d, const u32* a, const u32* b) {
    asm volatile("mma.sync.aligned.m16n8k16.row.col.f32.f16.f16.f32 "
                 "{%0,%1,%2,%3}, {%4,%5,%6,%7}, {%8,%9}, {%0,%1,%2,%3};"
                 : "+f"(d[0]), "+f"(d[1]), "+f"(d[2]), "+f"(d[3])
                 : "r"(a[0]), "r"(a[1]), "r"(a[2]), "r"(a[3]), "r"(b[0]), "r"(b[1]));
}
__device__ __forceinline__ void split_h16(float v, __half& h, __half& l) {
    h = __float2half_rn(v);
    l = __float2half_rn(v - __half2float(h));
}
__device__ __forceinline__ u32 pack2h(float v0, float v1) {
    __half h0 = __float2half_rn(v0), h1 = __float2half_rn(v1);
    return (u32)__half_as_ushort(h0) | ((u32)__half_as_ushort(h1) << 16);
}
__device__ __forceinline__ u32 pack_split2h(float v0, float v1, u32& lo_out) {
    __half h0, l0, h1, l1;
    split_h16(v0, h0, l0); split_h16(v1, h1, l1);
    lo_out = (u32)__half_as_ushort(l0) | ((u32)__half_as_ushort(l1) << 16);
    return (u32)__half_as_ushort(h0) | ((u32)__half_as_ushort(h1) << 16);
}
__device__ __forceinline__ void split_bf(float v, __nv_bfloat16& h, __nv_bfloat16& l) {
    h = __float2bfloat16(v);
    l = __float2bfloat16(v - __bfloat162float(h));
}
// gate-paired row -> j (j = gate*1024 + cell)
__device__ __forceinline__ int rowj(int nT, int n) {
    int half = n >> 6, m = n & 63;
    return (half * 2 + (m & 1)) * 1024 + nT * 32 + (m >> 1);
}

// ---------------- merged prep: convs + bias + flag init, one launch ----------------
__global__ void conv_all(const float* __restrict__ Whh, const float* __restrict__ Wih,
                         const float* __restrict__ Wout, const float* __restrict__ enc,
                         const float* __restrict__ bih, const float* __restrict__ bhh,
                         const float* __restrict__ bout)
{
    int b = blockIdx.x;
    int tid = threadIdx.x, w = tid >> 5, lane = tid & 31;

    if (b < 512) {                      // conv_w0: Whh -> g_wbf[0]
        int chunk = b & 15, nT = b >> 4;
        char* th = (char*)&g_wbf[0][nT][chunk][0];
#pragma unroll
        for (int r = 0; r < 16; r++) {
            int n = r * 8 + w;
            const float2 v2 = *(const float2*)&Whh[(size_t)rowj(nT, n) * 1024 + chunk * 64 + lane * 2];
            u32 off = swz((u32)(n * 128 + lane * 4));
            *(u32*)(th + off) = pack2h(v2.x, v2.y);
        }
    } else if (b < 640) {               // conv_wih -> g_pA (bf16 split)
        int idx = b - 512, oc = idx & 3, nT = idx >> 2;
        char* th = (char*)&g_pA[nT][oc][0][0];
        char* tl = th + 16384;
#pragma unroll
        for (int r = 0; r < 16; r++) {
            int n = r * 8 + w;
            const float2 v2 = *(const float2*)&Wih[(size_t)rowj(nT, n) * 256 + oc * 64 + lane * 2];
            __nv_bfloat16 h0, l0, h1, l1;
            split_bf(v2.x, h0, l0); split_bf(v2.y, h1, l1);
            u32 hi = (u32)__bfloat16_as_ushort(h0) | ((u32)__bfloat16_as_ushort(h1) << 16);
            u32 lo = (u32)__bfloat16_as_ushort(l0) | ((u32)__bfloat16_as_ushort(l1) << 16);
            u32 off = swz((u32)(n * 128 + lane * 4));
            *(u32*)(th + off) = hi;
            *(u32*)(tl + off) = lo;
        }
    } else if (b < 704) {               // conv_woutT -> g_pB (bf16 split)
        int idx = b - 640, oc = idx & 3, kc = idx >> 2;
        int k = tid & 63, og = tid >> 6;
        char* th = (char*)&g_pB[kc][oc][0][0];
        char* tl = th + 8192;
#pragma unroll
        for (int i = 0; i < 16; i++) {
            int oo = og * 16 + i;
            float v = Wout[(size_t)(oc * 64 + oo) * 1024 + kc * 64 + k];
            __nv_bfloat16 h, l; split_bf(v, h, l);
            u32 off = swz((u32)(k * 128 + oo * 2));
            *(__nv_bfloat16*)(th + off) = h;
            *(__nv_bfloat16*)(tl + off) = l;
        }
    } else if (b < 736) {               // conv_obf -> g_obf (fp16 split; hi used)
        int idx = b - 704, chunk = idx & 15, nOT = idx >> 4;
        char* th = (char*)&g_obf[nOT][chunk][0][0];
        char* tl = th + 16384;
#pragma unroll
        for (int r = 0; r < 16; r++) {
            int n = r * 8 + w;
            const float2 v2 = *(const float2*)&Wout[(size_t)(nOT * 128 + n) * 1024 + chunk * 64 + lane * 2];
            u32 lo, hi = pack_split2h(v2.x, v2.y, lo);
            u32 off = swz((u32)(n * 128 + lane * 4));
            *(u32*)(th + off) = hi;
            *(u32*)(tl + off) = lo;
        }
    } else if (b < 800) {               // conv_h0 -> g_hbf[0]
        int idx = b - 736, chunk = idx & 15, mT = idx >> 4;
        char* th = (char*)&g_hbf[0][mT][chunk][0];
#pragma unroll
        for (int r = 0; r < 16; r++) {
            int m = r * 8 + w;
            const float2 v2 = *(const float2*)&enc[(size_t)(mT * 128 + m) * 1024 + chunk * 64 + lane * 2];
            u32 off = swz((u32)(m * 128 + lane * 4));
            *(u32*)(th + off) = pack2h(v2.x, v2.y);
        }
    } else if (b < 804) {               // flag init
        int i = (b - 800) * 256 + tid;
        if (i < 516) g_bar[i] = 0;
    } else {                            // prep_bias: blocks 804..1315, warp per j
        int j = (b - 804) * 8 + w;
        float acc = 0.f;
#pragma unroll
        for (int i = 0; i < 8; i++) acc += Wih[(size_t)j * 256 + i * 32 + lane] * bout[i * 32 + lane];
#pragma unroll
        for (int o = 16; o; o >>= 1) acc += __shfl_xor_sync(0xFFFFFFFFu, acc, o);
        if (lane == 0) {
            float s = bih[j] + bhh[j];
            g_b0[j] = s;
            g_bf[j] = s + acc;
        }
    }
}

// ---------------- prep GEMM: g_wbf[1] = fp16(Whh + Wih @ Wout^T), bf16 3-pass -------
#define PREP_SMEM (128*1024 + 64*1024 + 1024)
__global__ __launch_bounds__(256, 1) void prep_mma(const float* __restrict__ Whh)
{
    extern __shared__ char smem[];
    u32 sb = (smem_u32(smem) + 1023) & ~1023u;
    int tid = threadIdx.x, lane = tid & 31, w = tid >> 5;
    int nT = blockIdx.x, kc = blockIdx.y;

    const char* srcA = (const char*)&g_pA[nT][0][0][0];
    const char* srcB = (const char*)&g_pB[kc][0][0][0];
#pragma unroll
    for (int r = 0; r < 32; r++) { int idx = r * 256 + tid; cpa16(sb + idx * 16, srcA + (size_t)idx * 16); }
#pragma unroll
    for (int r = 0; r < 16; r++) { int idx = r * 256 + tid; cpa16(sb + 131072 + idx * 16, srcB + (size_t)idx * 16); }
    CP_COMMIT(); CP_WAIT0();
    __syncthreads();

    int wm = w >> 1, wn = w & 1;
    const int aRow = ((lane >> 3) & 1) * 8 + (lane & 7);
    const int aKh  = lane >> 4;
    const int bRow = (lane >> 4) * 8 + (lane & 7);
    const int bKh  = (lane >> 3) & 1;

    float d[2][4][4] = {};
#pragma unroll
    for (int oc = 0; oc < 4; oc++) {
        u32 stA = sb + oc * 32768;
        u32 stB = sb + 131072 + oc * 16384;
#pragma unroll
        for (int k16 = 0; k16 < 4; k16++) {
            u32 aH[2][4], aL[2][4];
#pragma unroll
            for (int mi = 0; mi < 2; mi++) {
                u32 off = swz((u32)((wm * 32 + mi * 16 + aRow) * 128 + (k16 * 2 + aKh) * 16));
                ldsm4(aH[mi], stA + off);
                ldsm4(aL[mi], stA + 16384 + off);
            }
            u32 bH[2][4], bL[2][4];
#pragma unroll
            for (int bi = 0; bi < 2; bi++) {
                u32 off = swz((u32)((wn * 32 + bi * 16 + bRow) * 128 + (k16 * 2 + bKh) * 16));
                ldsm4(bH[bi], stB + off);
                ldsm4(bL[bi], stB + 8192 + off);
            }
#pragma unroll
            for (int mi = 0; mi < 2; mi++)
#pragma unroll
                for (int nj = 0; nj < 4; nj++) {
                    mma_bf16(d[mi][nj], aH[mi], &bH[nj >> 1][(nj & 1) * 2]);
                    mma_bf16(d[mi][nj], aH[mi], &bL[nj >> 1][(nj & 1) * 2]);
                    mma_bf16(d[mi][nj], aL[mi], &bH[nj >> 1][(nj & 1) * 2]);
                }
        }
    }

    char* th = (char*)&g_wbf[1][nT][kc][0];
#pragma unroll
    for (int mi = 0; mi < 2; mi++)
#pragma unroll
        for (int nj = 0; nj < 4; nj++)
#pragma unroll
            for (int rh = 0; rh < 2; rh++) {
                int n = wm * 32 + mi * 16 + (lane >> 2) + rh * 8;
                int j = rowj(nT, n);
                int k0l = wn * 32 + nj * 8 + 2 * (lane & 3);
                const float* wr = Whh + (size_t)j * 1024 + kc * 64 + k0l;
                u32 off = swz((u32)(n * 128 + k0l * 2));
                *(u32*)(th + off) = pack2h(d[mi][nj][rh * 2 + 0] + wr[0],
                                           d[mi][nj][rh * 2 + 1] + wr[1]);
            }
}

// ---------------- unified persistent kernel: 128 LSTM CTAs + 20 output workers -------
#define BRES_BYTES 163840
#define LSTAGE 32768
#define OSTG 32768
#define LSTM_SMEM (1024 + 1024 + BRES_BYTES + 2*LSTAGE)
__global__ __launch_bounds__(256, 1) void persist(const float* __restrict__ bout,
                                                  float* __restrict__ out)
{
    extern __shared__ char smem[];
    u32 sb = (smem_u32(smem) + 1023) & ~1023u;
    const int tid = threadIdx.x, lane = tid & 31, w = tid >> 5;
    const int bid = blockIdx.x;
    const int wm = w >> 2, wn = w & 3;
    const int aRow = ((lane >> 3) & 1) * 8 + (lane & 7);
    const int aKh  = lane >> 4;
    const int bRow = (lane >> 4) * 8 + (lane & 7);
    const int bKh  = (lane >> 3) & 1;

    if (bid < 128) {
        // ================= LSTM role =================
        const int mT = bid >> 5, nT = bid & 31;
        const u32 mb0 = sb, mb1 = sb + 16, mbP = sb + 32;
        const u32 sbBres  = sb + 1024;
        const u32 sbStage = sbBres + BRES_BYTES;

        if (tid == 0) {
            mbar_init(mb0, 1);
            mbar_init(mb1, 1);
            mbar_init(mbP, 1);
            asm volatile("fence.proxy.async.shared::cta;" ::: "memory");
        }
        __syncthreads();

        if (tid == 0) {
            const char* wres = (const char*)&g_wbf[1][nT][0];
            mbar_expect(mbP, BRES_BYTES);
#pragma unroll
            for (int c = 0; c < 10; c++)
                bulk_g2s(sbBres + c * 16384, wres + (size_t)c * 16384, 16384, mbP);

            const char* B1 = (const char*)&g_wbf[0][nT][0];
            const char* A1 = (const char*)&g_hbf[0][mT][0];
            mbar_expect(mb0, 32768);
            bulk_g2s(sbStage, A1, 16384, mb0);
            bulk_g2s(sbStage + 16384, B1, 16384, mb0);
            mbar_expect(mb1, 32768);
            bulk_g2s(sbStage + LSTAGE, A1 + 16384, 16384, mb1);
            bulk_g2s(sbStage + LSTAGE + 16384, B1 + 16384, 16384, mb1);
        }
        mbar_wait(mbP, 0);

        float bZ[2][4], bF[2][4];
#pragma unroll
        for (int cp = 0; cp < 2; cp++) {
            int cell = nT * 32 + wn * 8 + cp * 4 + (lane & 3);
#pragma unroll
            for (int g = 0; g < 4; g++) {
                bZ[cp][g] = g_b0[g * 1024 + cell];
                bF[cp][g] = g_bf[g * 1024 + cell];
            }
        }

        float creg[4][2][2];
#pragma unroll
        for (int mi = 0; mi < 4; mi++)
#pragma unroll
            for (int rh = 0; rh < 2; rh++)
#pragma unroll
                for (int cp = 0; cp < 2; cp++) creg[mi][rh][cp] = 0.f;

        u32 ph0 = 0, ph1 = 0;

        for (int t = 1; t <= 128; t++) {
            const int first = (t == 1);
            const char* srcA = (const char*)&g_hbf[t - 1][mT][0];
            const char* srcB = first ? (const char*)&g_wbf[0][nT][0]
                                     : (const char*)&g_wbf[1][nT][0];

            float d[4][4][4];
#pragma unroll
            for (int mi = 0; mi < 4; mi++)
#pragma unroll
                for (int nj = 0; nj < 4; nj++)
#pragma unroll
                    for (int q = 0; q < 4; q++) d[mi][nj][q] = 0.f;

            for (int c = 0; c < 16; c++) {
                int s = c & 1;
                u32 mbs = s ? mb1 : mb0;
                if (s) { mbar_wait(mb1, ph1); ph1 ^= 1; }
                else   { mbar_wait(mb0, ph0); ph0 ^= 1; }
                u32 stA = sbStage + s * LSTAGE;
                u32 stB = (!first && c < 10) ? (sbBres + c * 16384) : (stA + 16384);
#pragma unroll
                for (int k16 = 0; k16 < 4; k16++) {
                    u32 aH[4][4];
#pragma unroll
                    for (int mi = 0; mi < 4; mi++) {
                        u32 off = swz((u32)((wm * 64 + mi * 16 + aRow) * 128 + (k16 * 2 + aKh) * 16));
                        ldsm4(aH[mi], stA + off);
                    }
                    u32 bIFh[4], bGOh[4];
                    {
                        u32 offIF = swz((u32)((wn * 16 + bRow) * 128 + (k16 * 2 + bKh) * 16));
                        u32 offGO = swz((u32)((64 + wn * 16 + bRow) * 128 + (k16 * 2 + bKh) * 16));
                        ldsm4(bIFh, stB + offIF);
                        ldsm4(bGOh, stB + offGO);
                    }
#pragma unroll
                    for (int mi = 0; mi < 4; mi++)
#pragma unroll
                        for (int nj = 0; nj < 2; nj++) {
                            mma_f16(d[mi][nj],     aH[mi], &bIFh[nj * 2]);
                            mma_f16(d[mi][nj + 2], aH[mi], &bGOh[nj * 2]);
                        }
                }
                __syncthreads();   // all warps done with stage s -> safe to refill
                if (tid == 0 && c + 2 < 16) {
                    int cn = c + 2;
                    int bStream = (first || cn >= 10);
                    mbar_expect(mbs, bStream ? 32768u : 16384u);
                    bulk_g2s(stA, srcA + (size_t)cn * 16384, 16384, mbs);
                    if (bStream)
                        bulk_g2s(stA + 16384, srcB + (size_t)cn * 16384, 16384, mbs);
                }
            }

            // ---- epilogue: cell update (c in regs) + emit next A tile (hi-only) ----
            {
                const int chunk = nT >> 1;
                char* dh = (char*)&g_hbf[t][mT][chunk][0];
#pragma unroll
                for (int mi = 0; mi < 4; mi++)
#pragma unroll
                    for (int rh = 0; rh < 2; rh++) {
                        int bl = wm * 64 + mi * 16 + (lane >> 2) + rh * 8;
#pragma unroll
                        for (int cp = 0; cp < 2; cp++) {
                            int cl = wn * 8 + cp * 4 + (lane & 3);
                            float gi = d[mi][cp][rh * 2 + 0]     + (first ? bZ[cp][0] : bF[cp][0]);
                            float gf = d[mi][cp][rh * 2 + 1]     + (first ? bZ[cp][1] : bF[cp][1]);
                            float gg = d[mi][cp + 2][rh * 2 + 0] + (first ? bZ[cp][2] : bF[cp][2]);
                            float go = d[mi][cp + 2][rh * 2 + 1] + (first ? bZ[cp][3] : bF[cp][3]);
                            float cold = first ? 0.f : creg[mi][rh][cp];
                            float cn = sigm(gf) * cold + sigm(gi) * tanhf(gg);
                            float hn = sigm(go) * tanhf(cn);
                            creg[mi][rh][cp] = cn;
                            int kin = (nT & 1) * 32 + cl;
                            u32 off = swz((u32)(bl * 128 + kin * 2));
                            *(__half*)(dh + off) = __float2half_rn(hn);
                        }
                    }
            }

            __syncthreads();                 // all epilogue STGs issued
            if (tid == 0) {
                asm volatile("fence.release.gpu;" ::: "memory");
                u32* bp = &g_bar[t * 4 + mT];
                asm volatile("red.relaxed.gpu.global.add.u32 [%0], %1;" :: "l"(bp), "r"(1u) : "memory");
                if (t < 128) {
                    u32 v;
                    asm volatile("ld.relaxed.gpu.global.u32 %0, [%1];" : "=r"(v) : "l"(bp) : "memory");
                    while (v < 32) {
                        asm volatile("nanosleep.u32 32;");
                        asm volatile("ld.relaxed.gpu.global.u32 %0, [%1];" : "=r"(v) : "l"(bp) : "memory");
                    }
                    asm volatile("fence.acquire.gpu;" ::: "memory");
                    const char* An = (const char*)&g_hbf[t][mT][0];
                    mbar_expect(mb0, 16384);
                    bulk_g2s(sbStage, An, 16384, mb0);
                    mbar_expect(mb1, 16384);
                    bulk_g2s(sbStage + LSTAGE, An + 16384, 16384, mb1);
                }
            }
            if (t < 128) __syncthreads();
        }
    } else {
        // ================= output worker role =================
        const int wk = bid - 128;   // 0..19
        const u32 mb0 = sb, mb1 = sb + 16;
        const u32 stg = sb + 1024;

        if (tid == 0) {
            mbar_init(mb0, 1);
            mbar_init(mb1, 1);
            asm volatile("fence.proxy.async.shared::cta;" ::: "memory");
        }
        __syncthreads();

        u32 ph0 = 0, ph1 = 0;

        for (int job = wk; job < 1024; job += 20) {
            const int t   = (job >> 3) + 1;       // h step 1..128
            const int mT  = job & 3;
            const int nOT = (job >> 2) & 1;

            if (tid == 0) {
                const u32* bp = &g_bar[t * 4 + mT];
                u32 v;
                asm volatile("ld.relaxed.gpu.global.u32 %0, [%1];" : "=r"(v) : "l"(bp) : "memory");
                while (v < 32) {
                    asm volatile("nanosleep.u32 64;");
                    asm volatile("ld.relaxed.gpu.global.u32 %0, [%1];" : "=r"(v) : "l"(bp) : "memory");
                }
                asm volatile("fence.acquire.gpu;" ::: "memory");
            }
            __syncthreads();

            const char* srcA = (const char*)&g_hbf[t][mT][0];       // 16KB/chunk
            const char* srcB = (const char*)&g_obf[nOT][0][0][0];   // hi at +0, 32KB stride

            if (tid == 0) {
                mbar_expect(mb0, 32768);
                bulk_g2s(stg, srcA, 16384, mb0);
                bulk_g2s(stg + 16384, srcB, 16384, mb0);
                mbar_expect(mb1, 32768);
                bulk_g2s(stg + OSTG, srcA + 16384, 16384, mb1);
                bulk_g2s(stg + OSTG + 16384, srcB + 32768, 16384, mb1);
            }

            float d[4][4][4];
#pragma unroll
            for (int mi = 0; mi < 4; mi++)
#pragma unroll
                for (int nj = 0; nj < 4; nj++)
#pragma unroll
                    for (int q = 0; q < 4; q++) d[mi][nj][q] = 0.f;

            for (int c = 0; c < 16; c++) {
                int s = c & 1;
                u32 mbs = s ? mb1 : mb0;
                if (s) { mbar_wait(mb1, ph1); ph1 ^= 1; }
                else   { mbar_wait(mb0, ph0); ph0 ^= 1; }
                u32 stA = stg + s * OSTG;
                u32 stB = stA + 16384;
#pragma unroll
                for (int k16 = 0; k16 < 4; k16++) {
                    u32 aH[4][4];
#pragma unroll
                    for (int mi = 0; mi < 4; mi++) {
                        u32 off = swz((u32)((wm * 64 + mi * 16 + aRow) * 128 + (k16 * 2 + aKh) * 16));
                        ldsm4(aH[mi], stA + off);
                    }
                    u32 bH[2][4];
#pragma unroll
                    for (int bi = 0; bi < 2; bi++) {
                        u32 off = swz((u32)((wn * 32 + bi * 16 + bRow) * 128 + (k16 * 2 + bKh) * 16));
                        ldsm4(bH[bi], stB + off);
                    }
#pragma unroll
                    for (int mi = 0; mi < 4; mi++)
#pragma unroll
                        for (int nj = 0; nj < 4; nj++)
                            mma_f16(d[mi][nj], aH[mi], &bH[nj >> 1][(nj & 1) * 2]);
                }
                __syncthreads();
                if (tid == 0 && c + 2 < 16) {
                    int cn = c + 2;
                    mbar_expect(mbs, 32768);
                    bulk_g2s(stA, srcA + (size_t)cn * 16384, 16384, mbs);
                    bulk_g2s(stB, srcB + (size_t)cn * 32768, 16384, mbs);
                }
            }

#pragma unroll
            for (int mi = 0; mi < 4; mi++)
#pragma unroll
                for (int nj = 0; nj < 4; nj++)
#pragma unroll
                    for (int rh = 0; rh < 2; rh++) {
                        int bl = wm * 64 + mi * 16 + (lane >> 2) + rh * 8;
                        int b = mT * 128 + bl;
                        int o = nOT * 128 + wn * 32 + nj * 8 + 2 * (lane & 3);
                        float2 v = make_float2(d[mi][nj][rh * 2 + 0] + bout[o],
                                               d[mi][nj][rh * 2 + 1] + bout[o + 1]);
                        *(float2*)&out[(size_t)b * 32768 + (size_t)(t - 1) * 256 + o] = v;
                    }
        }
    }
}

// ---------------- launch ----------------
extern "C" void kernel_launch(void* const* d_in, const int* in_sizes, int n_in,
                              void* d_out, int out_size)
{
    const float *enc = nullptr, *Wih = nullptr, *Whh = nullptr;
    const float *bih = nullptr, *bhh = nullptr, *Wout = nullptr, *bout = nullptr;
    for (int i = 0; i < n_in; i++) {
        int s = in_sizes[i];
        if      (s == 512 * 1024)  enc  = (const float*)d_in[i];
        else if (s == 4096 * 256)  Wih  = (const float*)d_in[i];
        else if (s == 4096 * 1024) Whh  = (const float*)d_in[i];
        else if (s == 4096)        { if (!bih) bih = (const float*)d_in[i]; else bhh = (const float*)d_in[i]; }
        else if (s == 256 * 1024)  Wout = (const float*)d_in[i];
        else if (s == 256)         bout = (const float*)d_in[i];
    }
    if (!enc || !Wih || !Whh || !bih || !bhh || !Wout || !bout) return;

    cudaFuncSetAttribute(prep_mma, cudaFuncAttributeMaxDynamicSharedMemorySize, PREP_SMEM);
    cudaFuncSetAttribute(persist,  cudaFuncAttributeMaxDynamicSharedMemorySize, LSTM_SMEM);

    conv_all<<<1316, 256>>>(Whh, Wih, Wout, enc, bih, bhh, bout);
    prep_mma<<<dim3(32, 16), 256, PREP_SMEM>>>(Whh);
    persist<<<148, 256, LSTM_SMEM>>>(bout, (float*)d_out);
    (void)out_size;
}